// round 12
// baseline (speedup 1.0000x reference)
#include <cuda_runtime.h>
#include <cuda_fp16.h>
#include <cstdint>
#include <math.h>

#define BATCH 8
#define CH    256
#define HWP   4096   // 64*64

// ---------------- scratch (static device allocations; no cudaMalloc) ----------
__device__ float g_comp [BATCH*128*HWP];
__device__ float g_part [4*BATCH*64*HWP];   // k2 ci-split partials (33.5 MB)
__device__ float g_kw   [BATCH*HWP*36];
__device__ float g_kwsum[BATCH*HWP*9];
__device__ float g_gmap [BATCH*HWP];
__device__ float g_enh  [BATCH*CH*HWP];
__device__ float g_psum [BATCH*CH*16];      // per-(b,c,rowblk) enh partial sums
__device__ float g_pool_x[BATCH*CH];
__device__ float g_gate  [BATCH*CH];

// ---------------- helpers ------------------------------------------------------
__device__ __forceinline__ uint32_t s2u(const void* p){
  uint32_t a; asm("{ .reg .u64 t; cvta.to.shared.u64 t, %1; cvt.u32.u64 %0, t; }"
                  : "=r"(a) : "l"(p)); return a;
}
__device__ __forceinline__ uint16_t f16r(float v){
  __half h = __float2half_rn(v);
  return __half_as_ushort(h);
}
__device__ __forceinline__ void ldmx4(uint32_t r[4], uint32_t addr){
  asm volatile("ldmatrix.sync.aligned.m8n8.x4.shared.b16 {%0,%1,%2,%3}, [%4];"
               : "=r"(r[0]), "=r"(r[1]), "=r"(r[2]), "=r"(r[3]) : "r"(addr));
}
__device__ __forceinline__ void mma_f16(float c[4], const uint32_t a[4],
                                        uint32_t b0, uint32_t b1){
  asm volatile("mma.sync.aligned.m16n8k16.row.col.f32.f16.f16.f32 "
               "{%0,%1,%2,%3},{%4,%5,%6,%7},{%8,%9},{%0,%1,%2,%3};"
               : "+f"(c[0]), "+f"(c[1]), "+f"(c[2]), "+f"(c[3])
               : "r"(a[0]), "r"(a[1]), "r"(a[2]), "r"(a[3]), "r"(b0), "r"(b1));
}

// ================= implicit-GEMM conv on HMMA fp16 (single-pass) ==============
// MODE 0: dense (k1). MODE 1: grouped (k4) + per-channel rowblk sums to g_psum.
// MODE 2: ci-split (k2), raw partials out.
// EPI: 0 = +bias, 2 = raw
template<int CI, int CI_TOT, int TAPS, int EPI, int MODE>
__global__ __launch_bounds__(256, 2) void conv_mma(
    const float* __restrict__ in, const float* __restrict__ W,
    float* __restrict__ out, const float* __restrict__ bias) {
  extern __shared__ char sm[];
  constexpr uint32_t OP = 0;                              // pixel plane 19008 B
  constexpr uint32_t OW = 6*66*48;                        // 19008

  const int tid = threadIdx.x;
  const int lane = tid & 31, wid = tid >> 5;
  const int wy = wid >> 1, wx = wid & 1;                  // 4 m-warps x 2 n-warps
  const int g = lane >> 2, tq = lane & 3;
  const int rowblk = blockIdx.x;                          // 4 image rows
  const int cob = blockIdx.y;
  const int co0 = (MODE == 2) ? 0 : cob * 64;
  const int b = blockIdx.z;
  const int in_off = (MODE == 0) ? 0 : cob * CI;
  const float* inb = in + ((size_t)b*CI_TOT + in_off)*HWP;
  const uint32_t sbase = s2u(sm);

  float cacc[4][4][4];
  #pragma unroll
  for (int mm = 0; mm < 4; mm++)
    #pragma unroll
    for (int nn = 0; nn < 4; nn++)
      #pragma unroll
      for (int j = 0; j < 4; j++) cacc[mm][nn][j] = 0.f;

  for (int cb = 0; cb < CI/16; cb++) {
    __syncthreads();
    // ---- pixel tile [6 rows][66 cols][16 ci] fp16, 48B slot stride ----
    for (int i = tid; i < 792; i += 256) {
      int half = i & 1, slot = i >> 1;
      int r = slot / 66, c = slot - r*66;
      int y = rowblk*4 + r - 1, xx = c - 1;
      bool ok = ((unsigned)y < 64u) && ((unsigned)xx < 64u);
      const float* src = inb + (size_t)(cb*16 + half*8)*HWP + y*64 + xx;
      uint32_t hw[4];
      #pragma unroll
      for (int jj = 0; jj < 4; jj++) {
        float v0 = ok ? src[(size_t)(2*jj)*HWP]   : 0.f;
        float v1 = ok ? src[(size_t)(2*jj+1)*HWP] : 0.f;
        hw[jj] = (uint32_t)f16r(v0) | ((uint32_t)f16r(v1) << 16);
      }
      uint32_t boff = (uint32_t)slot*48 + half*16;
      *(uint4*)(sm + OP + boff) = make_uint4(hw[0],hw[1],hw[2],hw[3]);
    }
    // ---- weight tile [tap][64 co][16 ci re-paired] fp16 ----
    constexpr int PERM = TAPS*4;   // float4 per co-row for this ci-block
    for (int i = tid; i < 64*PERM; i += 256) {
      int m = i / PERM, q = i - m*PERM;
      size_t wb;
      if (MODE == 2) wb = ((size_t)m*CI_TOT + cob*CI + cb*16);
      else           wb = ((size_t)(co0 + m)*CI + cb*16);
      const float* wm = W + wb*TAPS;
      float4 v = *(const float4*)(wm + q*4);
      #pragma unroll
      for (int j = 0; j < 4; j++) {
        int e = q*4 + j;
        int ci = e / TAPS, t = e - ci*TAPS;
        int pos = ((ci & 7) >> 1)*4 + (ci >> 3)*2 + (ci & 1);
        uint32_t off = (uint32_t)((t*64 + m)*16 + pos)*2;
        *(uint16_t*)(sm + OW + off) = f16r((&v.x)[j]);
      }
    }
    __syncthreads();
    // ---- taps: shift pixel pointers, mma ----
    #pragma unroll 1
    for (int tap = 0; tap < TAPS; tap++) {
      int dy = (TAPS == 9) ? tap/3 - 1 : 0;
      int dx = (TAPS == 9) ? tap - (tap/3)*3 - 1 : 0;
      uint32_t ah[4][4];
      #pragma unroll
      for (int mm = 0; mm < 4; mm++) {
        int pxm = wy*64 + mm*16 + (lane & 15);
        int rr = (pxm >> 6) + 1 + dy;
        int cc = (pxm & 63) + 1 + dx;
        uint32_t boff = (uint32_t)(rr*66 + cc)*48 + ((lane >> 4) & 1)*16;
        ldmx4(ah[mm], sbase + OP + boff);
      }
      #pragma unroll
      for (int nn = 0; nn < 4; nn++) {
        int cof = wx*32 + nn*8 + g;
        uint32_t woff = (uint32_t)(tap*64 + cof)*32 + tq*8;
        uint2 bh = *(const uint2*)(sm + OW + woff);
        #pragma unroll
        for (int mm = 0; mm < 4; mm++) {
          mma_f16(cacc[mm][nn], ah[mm], bh.x, bh.y);
        }
      }
    }
  }
  // ---- epilogue: frags -> smem stage (stride 260 = conflict-free) -> gmem ----
  __syncthreads();
  float* osm = (float*)sm;
  #pragma unroll
  for (int mm = 0; mm < 4; mm++)
    #pragma unroll
    for (int nn = 0; nn < 4; nn++) {
      int px  = wy*64 + mm*16 + g;
      int col = wx*32 + nn*8 + tq*2;
      osm[(col  )*260 + px    ] = cacc[mm][nn][0];
      osm[(col+1)*260 + px    ] = cacc[mm][nn][1];
      osm[(col  )*260 + px + 8] = cacc[mm][nn][2];
      osm[(col+1)*260 + px + 8] = cacc[mm][nn][3];
    }
  __syncthreads();
  for (int i = tid; i < 16384; i += 256) {
    int col = i >> 8, px = i & 255;
    float v = osm[col*260 + px];
    int cg = co0 + col;
    if (EPI == 0) v += bias[cg];
    size_t obase;
    if (MODE == 2) obase = ((size_t)cob*BATCH*64 + (size_t)b*64 + cg)*HWP;
    else           obase = ((size_t)b*(gridDim.y*64) + cg)*HWP;
    out[obase + rowblk*256 + px] = v;
  }
  if (MODE == 1) {
    // per-channel partial sum over this CTA's 256 px (deterministic)
    int col = tid >> 2, quarter = tid & 3;
    const float* basep = osm + col*260 + quarter*64;
    float s = 0.f;
    #pragma unroll 16
    for (int p = 0; p < 64; p++) s += basep[p];
    s += __shfl_down_sync(0xffffffffu, s, 2);
    s += __shfl_down_sync(0xffffffffu, s, 1);
    if (quarter == 0)
      g_psum[((size_t)b*256 + cob*64 + col)*16 + rowblk] = s;
  }
}

// ---------------- K3: combine partials + BN + SiLU + 1x1 conv + softmax -------
__global__ __launch_bounds__(256) void k3_kw(const float* __restrict__ Wkp2,
    const float* __restrict__ bkp2, const float* __restrict__ bkp1,
    const float* __restrict__ g1, const float* __restrict__ be1,
    const float* __restrict__ m1, const float* __restrict__ v1) {
  __shared__ float wst[64][40];      // transposed [ci][j], padded row
  __shared__ float bs[36];
  __shared__ float scs[64], shs[64];
  __shared__ float part[3][64][37];  // odd stride -> conflict-free
  int tid = threadIdx.x;
  for (int i = tid; i < 2304; i += 256) {
    int j = i >> 6, ci = i & 63;
    wst[ci][j] = Wkp2[i];
  }
  if (tid < 36) bs[tid] = bkp2[tid];
  if (tid >= 64 && tid < 128) {
    int c = tid - 64;
    float sc = g1[c]*rsqrtf(v1[c]+1e-5f);
    scs[c] = sc;
    shs[c] = be1[c] - m1[c]*sc + bkp1[c]*sc;
  }
  __syncthreads();
  int quart = tid >> 6;              // ci quarter
  int pl = tid & 63;
  int gp = blockIdx.x*64 + pl;       // 512 blocks x 64 px = 32768
  int b = gp >> 12, p = gp & 4095;
  const int SL = BATCH*64*HWP;
  float acc[36];
  #pragma unroll
  for (int j=0;j<36;j++) acc[j]=0.f;
  const float* pb = g_part + (size_t)(b*64 + quart*16)*HWP + p;
  #pragma unroll 2
  for (int ci=0; ci<16; ci++) {
    size_t o = (size_t)ci*HWP;
    float v = pb[o] + pb[o+SL] + pb[o+2*(size_t)SL] + pb[o+3*(size_t)SL];
    int cg = quart*16 + ci;
    v = v*scs[cg] + shs[cg];
    float tv = v/(1.f+expf(-v));
    const float4* wp = (const float4*)&wst[cg][0];
    #pragma unroll
    for (int q=0;q<9;q++) {
      float4 w = wp[q];
      acc[4*q+0] += w.x*tv; acc[4*q+1] += w.y*tv;
      acc[4*q+2] += w.z*tv; acc[4*q+3] += w.w*tv;
    }
  }
  if (quart) {
    #pragma unroll
    for (int j=0;j<36;j++) part[quart-1][pl][j] = acc[j];
  }
  __syncthreads();
  if (!quart) {
    #pragma unroll
    for (int j=0;j<36;j++)
      acc[j] += part[0][pl][j] + part[1][pl][j] + part[2][pl][j] + bs[j];
    float ks[9];
    #pragma unroll
    for (int k=0;k<9;k++) ks[k]=0.f;
    float* kwp = g_kw + (size_t)gp*36;
    #pragma unroll
    for (int s=0;s<4;s++) {
      float m = acc[s*9];
      #pragma unroll
      for (int k=1;k<9;k++) m = fmaxf(m, acc[s*9+k]);
      float e[9]; float sum=0.f;
      #pragma unroll
      for (int k=0;k<9;k++){ e[k]=expf(acc[s*9+k]-m); sum+=e[k]; }
      float inv = 1.f/sum;
      #pragma unroll
      for (int k=0;k<9;k++){ float v=e[k]*inv; kwp[s*9+k]=v; ks[k]+=v; }
    }
    float* ksp = g_kwsum + (size_t)gp*9;
    #pragma unroll
    for (int k=0;k<9;k++) ksp[k]=ks[k];
  }
}

// ---------------- K3b: g map = 3x3 box correlation of kwsum -------------------
__global__ void k3b_gmap() {
  int gp = blockIdx.x*256 + threadIdx.x;
  int b = gp >> 12, p = gp & 4095;
  int i = p >> 6, j = p & 63;
  float s = 0.f;
  #pragma unroll
  for (int ih=0; ih<3; ih++)
    #pragma unroll
    for (int iw=0; iw<3; iw++) {
      int h = i + 1 - ih, w = j + 1 - iw;
      if ((unsigned)h < 64u && (unsigned)w < 64u)
        s += g_kwsum[(size_t)(b*4096 + h*64 + w)*9 + ih*3 + iw];
    }
  g_gmap[gp] = s;
}

// ---------------- K5b: pool x*gmap (main, after k3b) ---------------------------
__global__ __launch_bounds__(256) void k5b_pool(const float* __restrict__ x){
  int bc = blockIdx.x;
  int b = bc >> 8;
  const float* xp = x + (size_t)bc*HWP;
  const float* gp = g_gmap + (size_t)b*HWP;
  int tid = threadIdx.x;
  float s = 0.f;
  for (int i = tid; i < HWP; i += 256) s += xp[i]*gp[i];
  __shared__ float r[256];
  r[tid]=s; __syncthreads();
  for (int st=128; st>0; st>>=1) {
    if (tid < st) r[tid]+=r[tid+st];
    __syncthreads();
  }
  if (tid==0) g_pool_x[bc] = r[0];
}

// ---------------- K6: SE gate ---------------------------------------------------
__global__ __launch_bounds__(256) void k6_gate(const float* __restrict__ Wg1,
    const float* __restrict__ bg1, const float* __restrict__ Wg2,
    const float* __restrict__ bg2) {
  int b = blockIdx.x, tid = threadIdx.x;
  __shared__ float pl[256], hid[64];
  {
    const float4* ps = (const float4*)&g_psum[((size_t)b*256 + tid)*16];
    float se = 0.f;
    #pragma unroll
    for (int q = 0; q < 4; q++) {
      float4 v = ps[q];
      se += v.x + v.y + v.z + v.w;
    }
    pl[tid] = g_pool_x[b*256+tid]*(1.f/16384.f) + se*(1.f/4096.f);
  }
  __syncthreads();
  if (tid < 64) {
    float a = bg1[tid];
    for (int ci=0; ci<256; ci++) a += Wg1[tid*256+ci]*pl[ci];
    hid[tid] = a / (1.f + expf(-a));
  }
  __syncthreads();
  float a = bg2[tid];
  for (int j=0;j<64;j++) a += Wg2[tid*64+j]*hid[j];
  g_gate[b*256+tid] = 1.f/(1.f+expf(-a));
}

// ---------------- K7: reassembly + bilinear up + gate -> output ----------------
// Block: 4 h-rows x 64 cols x 8 channels. One thread = one (h,col) pixel.
__global__ __launch_bounds__(256, 3) void k7_fused(const float* __restrict__ x,
                                                   float* __restrict__ out) {
  extern __shared__ float sm7[];
  float* xs = sm7;                 // [8][6][66]
  float* es = sm7 + 8*6*66;        // [8][6][64]
  const int tid = threadIdx.x;
  const int c0 = blockIdx.x * 8;
  const int h0 = blockIdx.y * 4;
  const int b  = blockIdx.z;
  for (int i = tid; i < 8*6*66; i += 256) {
    int cc = i / 396, rem = i - cc*396;
    int rr = rem / 66, col = rem - rr*66 - 1;
    int y = h0 + rr - 1;
    float v = 0.f;
    if ((unsigned)y < 64u && (unsigned)col < 64u)
      v = x[((size_t)(b*CH)+c0+cc)*HWP + y*64 + col];
    xs[i] = v;
  }
  for (int i = tid; i < 8*6*64; i += 256) {
    int cc = i / 384, rem = i - cc*384;
    int rr = rem >> 6, col = rem & 63;
    int y = min(max(h0 + rr - 1, 0), 63);
    es[i] = g_enh[((size_t)(b*CH)+c0+cc)*HWP + y*64 + col];
  }
  __syncthreads();
  const int r = tid >> 6, col = tid & 63;
  const int h = h0 + r;
  float kp[36];
  {
    const float4* kq = (const float4*)(g_kw + ((size_t)(b*4096 + h*64 + col))*36);
    #pragma unroll
    for (int j = 0; j < 9; j++) {
      float4 v = kq[j];
      kp[4*j] = v.x; kp[4*j+1] = v.y; kp[4*j+2] = v.z; kp[4*j+3] = v.w;
    }
  }
  int base; float fw;
  if (col & 1) { base = (col - 1) >> 1; fw = 0.25f; }
  else         { base = (col >> 1) - 1; fw = 0.75f; }
  int cA0 = max(base, 0);
  int cB0 = base + 1;
  int cA1 = base + 32;
  int cB1 = min(base + 33, 63);
  float fw1 = 1.f - fw;
  #pragma unroll 1
  for (int cc = 0; cc < 8; cc++) {
    int c = c0 + cc;
    float gt = g_gate[b*256 + c];
    const float* xr = &xs[cc*396 + r*66 + col];
    float x00=xr[0],   x01=xr[1],   x02=xr[2];
    float x10=xr[66],  x11=xr[67],  x12=xr[68];
    float x20=xr[132], x21=xr[133], x22=xr[134];
    const float* er = &es[cc*384 + r*64];
    float rv[3][2];
    #pragma unroll
    for (int j = 0; j < 3; j++) {
      rv[j][0] = fw1*er[j*64 + cA0] + fw*er[j*64 + cB0];
      rv[j][1] = fw1*er[j*64 + cA1] + fw*er[j*64 + cB1];
    }
    float up[2][2];
    up[0][0] = 0.25f*rv[0][0] + 0.75f*rv[1][0];
    up[0][1] = 0.25f*rv[0][1] + 0.75f*rv[1][1];
    up[1][0] = 0.75f*rv[1][0] + 0.25f*rv[2][0];
    up[1][1] = 0.75f*rv[1][1] + 0.25f*rv[2][1];
    #pragma unroll
    for (int s = 0; s < 4; s++) {
      const float* kq = &kp[s*9];
      float ko = x00*kq[0]+x01*kq[1]+x02*kq[2]
               + x10*kq[3]+x11*kq[4]+x12*kq[5]
               + x20*kq[6]+x21*kq[7]+x22*kq[8];
      int di = s >> 1, dj = s & 1;
      size_t oidx = (size_t)(b*256 + c)*16384 + (size_t)(2*h+di)*128 + (size_t)(dj*64 + col);
      __stcs(&out[oidx], (ko + up[di][dj]) * gt);
    }
  }
}

// ---------------- launch --------------------------------------------------------
extern "C" void kernel_launch(void* const* d_in, const int* in_sizes, int n_in,
                              void* d_out, int out_size) {
  const float* x    = (const float*)d_in[0];
  const float* Wkc  = (const float*)d_in[1];
  const float* bkc  = (const float*)d_in[2];
  const float* Wkp1 = (const float*)d_in[3];
  const float* bkp1 = (const float*)d_in[4];
  const float* g1   = (const float*)d_in[5];
  const float* be1  = (const float*)d_in[6];
  const float* m1   = (const float*)d_in[7];
  const float* v1   = (const float*)d_in[8];
  const float* Wkp2 = (const float*)d_in[9];
  const float* bkp2 = (const float*)d_in[10];
  const float* Wdef = (const float*)d_in[11];
  const float* Wg1  = (const float*)d_in[12];
  const float* bg1  = (const float*)d_in[13];
  const float* Wg2  = (const float*)d_in[14];
  const float* bg2  = (const float*)d_in[15];
  float* out = (float*)d_out;

  float* comp = nullptr; float* part = nullptr; float* enh = nullptr;
  cudaGetSymbolAddress((void**)&comp, g_comp);
  cudaGetSymbolAddress((void**)&part, g_part);
  cudaGetSymbolAddress((void**)&enh,  g_enh);

  const int SM_CONV = 66560;
  const int SM_K7   = (8*6*66 + 8*6*64) * 4;   // 24960

  static cudaStream_t s2 = nullptr;
  static cudaEvent_t evFork = nullptr, evJoin = nullptr;
  if (s2 == nullptr) {
    cudaFuncSetAttribute((const void*)conv_mma<256,256,1,0,0>, cudaFuncAttributeMaxDynamicSharedMemorySize, SM_CONV);
    cudaFuncSetAttribute((const void*)conv_mma<32,128,9,2,2>,  cudaFuncAttributeMaxDynamicSharedMemorySize, SM_CONV);
    cudaFuncSetAttribute((const void*)conv_mma<64,256,9,2,1>,  cudaFuncAttributeMaxDynamicSharedMemorySize, SM_CONV);
    cudaFuncSetAttribute((const void*)k7_fused,                cudaFuncAttributeMaxDynamicSharedMemorySize, SM_K7);
    cudaStreamCreateWithFlags(&s2, cudaStreamNonBlocking);
    cudaEventCreateWithFlags(&evFork, cudaEventDisableTiming);
    cudaEventCreateWithFlags(&evJoin, cudaEventDisableTiming);
  }

  // ---- fork: k4 (with fused enh pool) on side stream; predictor chain on main
  cudaEventRecord(evFork, 0);
  cudaStreamWaitEvent(s2, evFork, 0);

  conv_mma<64,256,9,2,1><<<dim3(16,4,8), 256, SM_CONV, s2>>>(x, Wdef, enh, nullptr);

  conv_mma<256,256,1,0,0><<<dim3(16,2,8), 256, SM_CONV>>>(x, Wkc, comp, bkc);
  conv_mma<32,128,9,2,2><<<dim3(16,4,8), 256, SM_CONV>>>(comp, Wkp1, part, nullptr);
  k3_kw   <<<512, 256>>>(Wkp2, bkp2, bkp1, g1, be1, m1, v1);
  k3b_gmap<<<128, 256>>>();
  k5b_pool<<<2048, 256>>>(x);

  // ---- join: k6/k7 need enh + psum + pool_x ----
  cudaEventRecord(evJoin, s2);
  cudaStreamWaitEvent(0, evJoin, 0);

  k6_gate <<<8, 256>>>(Wg1, bg1, Wg2, bg2);
  k7_fused<<<dim3(32,16,8), 256, SM_K7>>>(x, out);
}

// round 13
// speedup vs baseline: 1.1842x; 1.1842x over previous
#include <cuda_runtime.h>
#include <cuda_fp16.h>
#include <cstdint>
#include <math.h>

#define BATCH 8
#define CH    256
#define HWP   4096   // 64*64

// ---------------- scratch (static device allocations; no cudaMalloc) ----------
__device__ float g_comp [BATCH*128*HWP];
__device__ float g_part [4*BATCH*64*HWP];   // k2 ci-split partials (33.5 MB)
__device__ float g_kw   [BATCH*HWP*36];
__device__ float g_kwsum[BATCH*HWP*9];
__device__ float g_gmap [BATCH*HWP];
__device__ float g_enh  [BATCH*CH*HWP];
__device__ float g_psum [BATCH*CH*16];      // per-(b,c,rowblk) enh partial sums
__device__ float g_pool_x[BATCH*CH];
__device__ float g_gate  [BATCH*CH];

// ---------------- helpers ------------------------------------------------------
__device__ __forceinline__ uint32_t s2u(const void* p){
  uint32_t a; asm("{ .reg .u64 t; cvta.to.shared.u64 t, %1; cvt.u32.u64 %0, t; }"
                  : "=r"(a) : "l"(p)); return a;
}
__device__ __forceinline__ uint16_t f16r(float v){
  __half h = __float2half_rn(v);
  return __half_as_ushort(h);
}
__device__ __forceinline__ void ldmx4(uint32_t r[4], uint32_t addr){
  asm volatile("ldmatrix.sync.aligned.m8n8.x4.shared.b16 {%0,%1,%2,%3}, [%4];"
               : "=r"(r[0]), "=r"(r[1]), "=r"(r[2]), "=r"(r[3]) : "r"(addr));
}
__device__ __forceinline__ void mma_f16(float c[4], const uint32_t a[4],
                                        uint32_t b0, uint32_t b1){
  asm volatile("mma.sync.aligned.m16n8k16.row.col.f32.f16.f16.f32 "
               "{%0,%1,%2,%3},{%4,%5,%6,%7},{%8,%9},{%0,%1,%2,%3};"
               : "+f"(c[0]), "+f"(c[1]), "+f"(c[2]), "+f"(c[3])
               : "r"(a[0]), "r"(a[1]), "r"(a[2]), "r"(a[3]), "r"(b0), "r"(b1));
}

// ================= implicit-GEMM conv on HMMA fp16 (single-pass) ==============
// MODE 0: dense (k1). MODE 1: grouped (k4) + per-channel rowblk sums to g_psum.
// MODE 2: ci-split (k2), raw partials out.
// EPI: 0 = +bias, 2 = raw
template<int CI, int CI_TOT, int TAPS, int EPI, int MODE>
__global__ __launch_bounds__(256, 2) void conv_mma(
    const float* __restrict__ in, const float* __restrict__ W,
    float* __restrict__ out, const float* __restrict__ bias) {
  extern __shared__ char sm[];
  constexpr uint32_t OP = 0;                              // pixel plane 19008 B
  constexpr uint32_t OW = 6*66*48;                        // 19008

  const int tid = threadIdx.x;
  const int lane = tid & 31, wid = tid >> 5;
  const int wy = wid >> 1, wx = wid & 1;                  // 4 m-warps x 2 n-warps
  const int g = lane >> 2, tq = lane & 3;
  const int rowblk = blockIdx.x;                          // 4 image rows
  const int cob = blockIdx.y;
  const int co0 = (MODE == 2) ? 0 : cob * 64;
  const int b = blockIdx.z;
  const int in_off = (MODE == 0) ? 0 : cob * CI;
  const float* inb = in + ((size_t)b*CI_TOT + in_off)*HWP;
  const uint32_t sbase = s2u(sm);

  float cacc[4][4][4];
  #pragma unroll
  for (int mm = 0; mm < 4; mm++)
    #pragma unroll
    for (int nn = 0; nn < 4; nn++)
      #pragma unroll
      for (int j = 0; j < 4; j++) cacc[mm][nn][j] = 0.f;

  for (int cb = 0; cb < CI/16; cb++) {
    __syncthreads();
    // ---- pixel tile [6 rows][66 cols][16 ci] fp16, 48B slot stride ----
    for (int i = tid; i < 792; i += 256) {
      int half = i & 1, slot = i >> 1;
      int r = slot / 66, c = slot - r*66;
      int y = rowblk*4 + r - 1, xx = c - 1;
      bool ok = ((unsigned)y < 64u) && ((unsigned)xx < 64u);
      const float* src = inb + (size_t)(cb*16 + half*8)*HWP + y*64 + xx;
      uint32_t hw[4];
      #pragma unroll
      for (int jj = 0; jj < 4; jj++) {
        float v0 = ok ? src[(size_t)(2*jj)*HWP]   : 0.f;
        float v1 = ok ? src[(size_t)(2*jj+1)*HWP] : 0.f;
        hw[jj] = (uint32_t)f16r(v0) | ((uint32_t)f16r(v1) << 16);
      }
      uint32_t boff = (uint32_t)slot*48 + half*16;
      *(uint4*)(sm + OP + boff) = make_uint4(hw[0],hw[1],hw[2],hw[3]);
    }
    // ---- weight tile [tap][64 co][16 ci re-paired] fp16 ----
    constexpr int PERM = TAPS*4;   // float4 per co-row for this ci-block
    for (int i = tid; i < 64*PERM; i += 256) {
      int m = i / PERM, q = i - m*PERM;
      size_t wb;
      if (MODE == 2) wb = ((size_t)m*CI_TOT + cob*CI + cb*16);
      else           wb = ((size_t)(co0 + m)*CI + cb*16);
      const float* wm = W + wb*TAPS;
      float4 v = *(const float4*)(wm + q*4);
      #pragma unroll
      for (int j = 0; j < 4; j++) {
        int e = q*4 + j;
        int ci = e / TAPS, t = e - ci*TAPS;
        int pos = ((ci & 7) >> 1)*4 + (ci >> 3)*2 + (ci & 1);
        uint32_t off = (uint32_t)((t*64 + m)*16 + pos)*2;
        *(uint16_t*)(sm + OW + off) = f16r((&v.x)[j]);
      }
    }
    __syncthreads();
    // ---- taps: shift pixel pointers, mma ----
    #pragma unroll 1
    for (int tap = 0; tap < TAPS; tap++) {
      int dy = (TAPS == 9) ? tap/3 - 1 : 0;
      int dx = (TAPS == 9) ? tap - (tap/3)*3 - 1 : 0;
      uint32_t ah[4][4];
      #pragma unroll
      for (int mm = 0; mm < 4; mm++) {
        int pxm = wy*64 + mm*16 + (lane & 15);
        int rr = (pxm >> 6) + 1 + dy;
        int cc = (pxm & 63) + 1 + dx;
        uint32_t boff = (uint32_t)(rr*66 + cc)*48 + ((lane >> 4) & 1)*16;
        ldmx4(ah[mm], sbase + OP + boff);
      }
      #pragma unroll
      for (int nn = 0; nn < 4; nn++) {
        int cof = wx*32 + nn*8 + g;
        uint32_t woff = (uint32_t)(tap*64 + cof)*32 + tq*8;
        uint2 bh = *(const uint2*)(sm + OW + woff);
        #pragma unroll
        for (int mm = 0; mm < 4; mm++) {
          mma_f16(cacc[mm][nn], ah[mm], bh.x, bh.y);
        }
      }
    }
  }
  // ---- epilogue: frags -> smem stage (stride 260 = conflict-free) -> gmem ----
  __syncthreads();
  float* osm = (float*)sm;
  #pragma unroll
  for (int mm = 0; mm < 4; mm++)
    #pragma unroll
    for (int nn = 0; nn < 4; nn++) {
      int px  = wy*64 + mm*16 + g;
      int col = wx*32 + nn*8 + tq*2;
      osm[(col  )*260 + px    ] = cacc[mm][nn][0];
      osm[(col+1)*260 + px    ] = cacc[mm][nn][1];
      osm[(col  )*260 + px + 8] = cacc[mm][nn][2];
      osm[(col+1)*260 + px + 8] = cacc[mm][nn][3];
    }
  __syncthreads();
  for (int i = tid; i < 16384; i += 256) {
    int col = i >> 8, px = i & 255;
    float v = osm[col*260 + px];
    int cg = co0 + col;
    if (EPI == 0) v += bias[cg];
    size_t obase;
    if (MODE == 2) obase = ((size_t)cob*BATCH*64 + (size_t)b*64 + cg)*HWP;
    else           obase = ((size_t)b*(gridDim.y*64) + cg)*HWP;
    out[obase + rowblk*256 + px] = v;
  }
  if (MODE == 1) {
    // per-channel partial sum over this CTA's 256 px (deterministic)
    int col = tid >> 2, quarter = tid & 3;
    const float* basep = osm + col*260 + quarter*64;
    float s = 0.f;
    #pragma unroll 16
    for (int p = 0; p < 64; p++) s += basep[p];
    s += __shfl_down_sync(0xffffffffu, s, 2);
    s += __shfl_down_sync(0xffffffffu, s, 1);
    if (quarter == 0)
      g_psum[((size_t)b*256 + cob*64 + col)*16 + rowblk] = s;
  }
}

// ---------------- K3: combine partials + BN + SiLU + 1x1 conv + softmax -------
__global__ __launch_bounds__(256) void k3_kw(const float* __restrict__ Wkp2,
    const float* __restrict__ bkp2, const float* __restrict__ bkp1,
    const float* __restrict__ g1, const float* __restrict__ be1,
    const float* __restrict__ m1, const float* __restrict__ v1) {
  __shared__ float wst[64][40];      // transposed [ci][j], padded row
  __shared__ float bs[36];
  __shared__ float scs[64], shs[64];
  __shared__ float part[3][64][37];  // odd stride -> conflict-free
  int tid = threadIdx.x;
  for (int i = tid; i < 2304; i += 256) {
    int j = i >> 6, ci = i & 63;
    wst[ci][j] = Wkp2[i];
  }
  if (tid < 36) bs[tid] = bkp2[tid];
  if (tid >= 64 && tid < 128) {
    int c = tid - 64;
    float sc = g1[c]*rsqrtf(v1[c]+1e-5f);
    scs[c] = sc;
    shs[c] = be1[c] - m1[c]*sc + bkp1[c]*sc;
  }
  __syncthreads();
  int quart = tid >> 6;              // ci quarter
  int pl = tid & 63;
  int gp = blockIdx.x*64 + pl;       // 512 blocks x 64 px = 32768
  int b = gp >> 12, p = gp & 4095;
  const int SL = BATCH*64*HWP;
  float acc[36];
  #pragma unroll
  for (int j=0;j<36;j++) acc[j]=0.f;
  const float* pb = g_part + (size_t)(b*64 + quart*16)*HWP + p;
  #pragma unroll 2
  for (int ci=0; ci<16; ci++) {
    size_t o = (size_t)ci*HWP;
    float v = pb[o] + pb[o+SL] + pb[o+2*(size_t)SL] + pb[o+3*(size_t)SL];
    int cg = quart*16 + ci;
    v = v*scs[cg] + shs[cg];
    float tv = v/(1.f+expf(-v));
    const float4* wp = (const float4*)&wst[cg][0];
    #pragma unroll
    for (int q=0;q<9;q++) {
      float4 w = wp[q];
      acc[4*q+0] += w.x*tv; acc[4*q+1] += w.y*tv;
      acc[4*q+2] += w.z*tv; acc[4*q+3] += w.w*tv;
    }
  }
  if (quart) {
    #pragma unroll
    for (int j=0;j<36;j++) part[quart-1][pl][j] = acc[j];
  }
  __syncthreads();
  if (!quart) {
    #pragma unroll
    for (int j=0;j<36;j++)
      acc[j] += part[0][pl][j] + part[1][pl][j] + part[2][pl][j] + bs[j];
    float ks[9];
    #pragma unroll
    for (int k=0;k<9;k++) ks[k]=0.f;
    float* kwp = g_kw + (size_t)gp*36;
    #pragma unroll
    for (int s=0;s<4;s++) {
      float m = acc[s*9];
      #pragma unroll
      for (int k=1;k<9;k++) m = fmaxf(m, acc[s*9+k]);
      float e[9]; float sum=0.f;
      #pragma unroll
      for (int k=0;k<9;k++){ e[k]=expf(acc[s*9+k]-m); sum+=e[k]; }
      float inv = 1.f/sum;
      #pragma unroll
      for (int k=0;k<9;k++){ float v=e[k]*inv; kwp[s*9+k]=v; ks[k]+=v; }
    }
    float* ksp = g_kwsum + (size_t)gp*9;
    #pragma unroll
    for (int k=0;k<9;k++) ksp[k]=ks[k];
  }
}

// ---------------- K3b: g map = 3x3 box correlation of kwsum -------------------
__global__ void k3b_gmap() {
  int gp = blockIdx.x*256 + threadIdx.x;
  int b = gp >> 12, p = gp & 4095;
  int i = p >> 6, j = p & 63;
  float s = 0.f;
  #pragma unroll
  for (int ih=0; ih<3; ih++)
    #pragma unroll
    for (int iw=0; iw<3; iw++) {
      int h = i + 1 - ih, w = j + 1 - iw;
      if ((unsigned)h < 64u && (unsigned)w < 64u)
        s += g_kwsum[(size_t)(b*4096 + h*64 + w)*9 + ih*3 + iw];
    }
  g_gmap[gp] = s;
}

// ---------------- K5b: pool x*gmap (main, after k3b) ---------------------------
__global__ __launch_bounds__(256) void k5b_pool(const float* __restrict__ x){
  int bc = blockIdx.x;
  int b = bc >> 8;
  const float* xp = x + (size_t)bc*HWP;
  const float* gp = g_gmap + (size_t)b*HWP;
  int tid = threadIdx.x;
  float s = 0.f;
  for (int i = tid; i < HWP; i += 256) s += xp[i]*gp[i];
  __shared__ float r[256];
  r[tid]=s; __syncthreads();
  for (int st=128; st>0; st>>=1) {
    if (tid < st) r[tid]+=r[tid+st];
    __syncthreads();
  }
  if (tid==0) g_pool_x[bc] = r[0];
}

// ---------------- K6: SE gate ---------------------------------------------------
__global__ __launch_bounds__(256) void k6_gate(const float* __restrict__ Wg1,
    const float* __restrict__ bg1, const float* __restrict__ Wg2,
    const float* __restrict__ bg2) {
  int b = blockIdx.x, tid = threadIdx.x;
  __shared__ float pl[256], hid[64];
  {
    const float4* ps = (const float4*)&g_psum[((size_t)b*256 + tid)*16];
    float se = 0.f;
    #pragma unroll
    for (int q = 0; q < 4; q++) {
      float4 v = ps[q];
      se += v.x + v.y + v.z + v.w;
    }
    pl[tid] = g_pool_x[b*256+tid]*(1.f/16384.f) + se*(1.f/4096.f);
  }
  __syncthreads();
  if (tid < 64) {
    float a = bg1[tid];
    for (int ci=0; ci<256; ci++) a += Wg1[tid*256+ci]*pl[ci];
    hid[tid] = a / (1.f + expf(-a));
  }
  __syncthreads();
  float a = bg2[tid];
  for (int j=0;j<64;j++) a += Wg2[tid*64+j]*hid[j];
  g_gate[b*256+tid] = 1.f/(1.f+expf(-a));
}

// ---------------- K7: reassembly + bilinear up + gate -> output ----------------
// Block: 4 h-rows x 64 cols x 16 channels (proven R11 shape).
__global__ __launch_bounds__(256, 2) void k7_fused(const float* __restrict__ x,
                                                   float* __restrict__ out) {
  extern __shared__ float sm7[];
  float* xs = sm7;                 // [16][6][66]
  float* es = sm7 + 16*6*66;       // [16][6][64]
  const int tid = threadIdx.x;
  const int c0 = blockIdx.x * 16;
  const int h0 = blockIdx.y * 4;
  const int b  = blockIdx.z;
  for (int i = tid; i < 16*6*66; i += 256) {
    int cc = i / 396, rem = i - cc*396;
    int rr = rem / 66, col = rem - rr*66 - 1;
    int y = h0 + rr - 1;
    float v = 0.f;
    if ((unsigned)y < 64u && (unsigned)col < 64u)
      v = x[((size_t)(b*CH)+c0+cc)*HWP + y*64 + col];
    xs[i] = v;
  }
  for (int i = tid; i < 16*6*64; i += 256) {
    int cc = i / 384, rem = i - cc*384;
    int rr = rem >> 6, col = rem & 63;
    int y = min(max(h0 + rr - 1, 0), 63);
    es[i] = g_enh[((size_t)(b*CH)+c0+cc)*HWP + y*64 + col];
  }
  __syncthreads();
  const int r = tid >> 6, col = tid & 63;
  const int h = h0 + r;
  float kp[36];
  {
    const float4* kq = (const float4*)(g_kw + ((size_t)(b*4096 + h*64 + col))*36);
    #pragma unroll
    for (int j = 0; j < 9; j++) {
      float4 v = kq[j];
      kp[4*j] = v.x; kp[4*j+1] = v.y; kp[4*j+2] = v.z; kp[4*j+3] = v.w;
    }
  }
  int base; float fw;
  if (col & 1) { base = (col - 1) >> 1; fw = 0.25f; }
  else         { base = (col >> 1) - 1; fw = 0.75f; }
  int cA0 = max(base, 0);
  int cB0 = base + 1;
  int cA1 = base + 32;
  int cB1 = min(base + 33, 63);
  float fw1 = 1.f - fw;
  #pragma unroll 1
  for (int cc = 0; cc < 16; cc++) {
    int c = c0 + cc;
    float gt = g_gate[b*256 + c];
    const float* xr = &xs[cc*396 + r*66 + col];
    float x00=xr[0],   x01=xr[1],   x02=xr[2];
    float x10=xr[66],  x11=xr[67],  x12=xr[68];
    float x20=xr[132], x21=xr[133], x22=xr[134];
    const float* er = &es[cc*384 + r*64];
    float rv[3][2];
    #pragma unroll
    for (int j = 0; j < 3; j++) {
      rv[j][0] = fw1*er[j*64 + cA0] + fw*er[j*64 + cB0];
      rv[j][1] = fw1*er[j*64 + cA1] + fw*er[j*64 + cB1];
    }
    float up[2][2];
    up[0][0] = 0.25f*rv[0][0] + 0.75f*rv[1][0];
    up[0][1] = 0.25f*rv[0][1] + 0.75f*rv[1][1];
    up[1][0] = 0.75f*rv[1][0] + 0.25f*rv[2][0];
    up[1][1] = 0.75f*rv[1][1] + 0.25f*rv[2][1];
    #pragma unroll
    for (int s = 0; s < 4; s++) {
      const float* kq = &kp[s*9];
      float ko = x00*kq[0]+x01*kq[1]+x02*kq[2]
               + x10*kq[3]+x11*kq[4]+x12*kq[5]
               + x20*kq[6]+x21*kq[7]+x22*kq[8];
      int di = s >> 1, dj = s & 1;
      size_t oidx = (size_t)(b*256 + c)*16384 + (size_t)(2*h+di)*128 + (size_t)(dj*64 + col);
      __stcs(&out[oidx], (ko + up[di][dj]) * gt);
    }
  }
}

// ---------------- launch --------------------------------------------------------
extern "C" void kernel_launch(void* const* d_in, const int* in_sizes, int n_in,
                              void* d_out, int out_size) {
  const float* x    = (const float*)d_in[0];
  const float* Wkc  = (const float*)d_in[1];
  const float* bkc  = (const float*)d_in[2];
  const float* Wkp1 = (const float*)d_in[3];
  const float* bkp1 = (const float*)d_in[4];
  const float* g1   = (const float*)d_in[5];
  const float* be1  = (const float*)d_in[6];
  const float* m1   = (const float*)d_in[7];
  const float* v1   = (const float*)d_in[8];
  const float* Wkp2 = (const float*)d_in[9];
  const float* bkp2 = (const float*)d_in[10];
  const float* Wdef = (const float*)d_in[11];
  const float* Wg1  = (const float*)d_in[12];
  const float* bg1  = (const float*)d_in[13];
  const float* Wg2  = (const float*)d_in[14];
  const float* bg2  = (const float*)d_in[15];
  float* out = (float*)d_out;

  float* comp = nullptr; float* part = nullptr; float* enh = nullptr;
  cudaGetSymbolAddress((void**)&comp, g_comp);
  cudaGetSymbolAddress((void**)&part, g_part);
  cudaGetSymbolAddress((void**)&enh,  g_enh);

  const int SM_CONV = 66560;
  const int SM_K7   = (16*6*66 + 16*6*64) * 4;   // 49920

  static cudaStream_t s2 = nullptr;
  static cudaEvent_t evFork = nullptr, evJoin = nullptr;
  if (s2 == nullptr) {
    cudaFuncSetAttribute((const void*)conv_mma<256,256,1,0,0>, cudaFuncAttributeMaxDynamicSharedMemorySize, SM_CONV);
    cudaFuncSetAttribute((const void*)conv_mma<32,128,9,2,2>,  cudaFuncAttributeMaxDynamicSharedMemorySize, SM_CONV);
    cudaFuncSetAttribute((const void*)conv_mma<64,256,9,2,1>,  cudaFuncAttributeMaxDynamicSharedMemorySize, SM_CONV);
    cudaFuncSetAttribute((const void*)k7_fused,                cudaFuncAttributeMaxDynamicSharedMemorySize, SM_K7);
    cudaStreamCreateWithFlags(&s2, cudaStreamNonBlocking);
    cudaEventCreateWithFlags(&evFork, cudaEventDisableTiming);
    cudaEventCreateWithFlags(&evJoin, cudaEventDisableTiming);
  }

  // ---- fork: k4 (with fused enh pool) on side stream; predictor chain on main
  cudaEventRecord(evFork, 0);
  cudaStreamWaitEvent(s2, evFork, 0);

  conv_mma<64,256,9,2,1><<<dim3(16,4,8), 256, SM_CONV, s2>>>(x, Wdef, enh, nullptr);

  conv_mma<256,256,1,0,0><<<dim3(16,2,8), 256, SM_CONV>>>(x, Wkc, comp, bkc);
  conv_mma<32,128,9,2,2><<<dim3(16,4,8), 256, SM_CONV>>>(comp, Wkp1, part, nullptr);
  k3_kw   <<<512, 256>>>(Wkp2, bkp2, bkp1, g1, be1, m1, v1);
  k3b_gmap<<<128, 256>>>();
  k5b_pool<<<2048, 256>>>(x);

  // ---- join: k6/k7 need enh + psum + pool_x ----
  cudaEventRecord(evJoin, s2);
  cudaStreamWaitEvent(0, evJoin, 0);

  k6_gate <<<8, 256>>>(Wg1, bg1, Wg2, bg2);
  k7_fused<<<dim3(16,16,8), 256, SM_K7>>>(x, out);
}

// round 14
// speedup vs baseline: 1.2360x; 1.0437x over previous
#include <cuda_runtime.h>
#include <cuda_fp16.h>
#include <cstdint>
#include <math.h>

#define BATCH 8
#define CH    256
#define HWP   4096   // 64*64

// ---------------- scratch (static device allocations; no cudaMalloc) ----------
__device__ float g_comp [BATCH*128*HWP];
__device__ float g_part [2*BATCH*64*HWP];   // k2 ci-split partials (16.8 MB)
__device__ float g_kw   [BATCH*HWP*36];
__device__ float g_kwsum[BATCH*HWP*9];
__device__ float g_gmap [BATCH*HWP];
__device__ float g_enh  [BATCH*CH*HWP];
__device__ float g_psum [BATCH*CH*16];      // per-(b,c,rowblk) enh partial sums
__device__ float g_pool_x[BATCH*CH];
__device__ float g_gate  [BATCH*CH];

// ---------------- helpers ------------------------------------------------------
__device__ __forceinline__ uint32_t s2u(const void* p){
  uint32_t a; asm("{ .reg .u64 t; cvta.to.shared.u64 t, %1; cvt.u32.u64 %0, t; }"
                  : "=r"(a) : "l"(p)); return a;
}
__device__ __forceinline__ uint16_t f16r(float v){
  __half h = __float2half_rn(v);
  return __half_as_ushort(h);
}
__device__ __forceinline__ void ldmx4(uint32_t r[4], uint32_t addr){
  asm volatile("ldmatrix.sync.aligned.m8n8.x4.shared.b16 {%0,%1,%2,%3}, [%4];"
               : "=r"(r[0]), "=r"(r[1]), "=r"(r[2]), "=r"(r[3]) : "r"(addr));
}
__device__ __forceinline__ void mma_f16(float c[4], const uint32_t a[4],
                                        uint32_t b0, uint32_t b1){
  asm volatile("mma.sync.aligned.m16n8k16.row.col.f32.f16.f16.f32 "
               "{%0,%1,%2,%3},{%4,%5,%6,%7},{%8,%9},{%0,%1,%2,%3};"
               : "+f"(c[0]), "+f"(c[1]), "+f"(c[2]), "+f"(c[3])
               : "r"(a[0]), "r"(a[1]), "r"(a[2]), "r"(a[3]), "r"(b0), "r"(b1));
}

// ================= implicit-GEMM conv on HMMA fp16 (single-pass) ==============
// MODE 0: dense (k1). MODE 1: grouped (k4) + per-channel rowblk sums to g_psum.
// MODE 2: ci-split (k2), raw partials out.
// EPI: 0 = +bias, 2 = raw
template<int CI, int CI_TOT, int TAPS, int EPI, int MODE>
__global__ __launch_bounds__(256, 2) void conv_mma(
    const float* __restrict__ in, const float* __restrict__ W,
    float* __restrict__ out, const float* __restrict__ bias) {
  extern __shared__ char sm[];
  constexpr uint32_t OP = 0;                              // pixel plane 19008 B
  constexpr uint32_t OW = 6*66*48;                        // 19008

  const int tid = threadIdx.x;
  const int lane = tid & 31, wid = tid >> 5;
  const int wy = wid >> 1, wx = wid & 1;                  // 4 m-warps x 2 n-warps
  const int g = lane >> 2, tq = lane & 3;
  const int rowblk = blockIdx.x;                          // 4 image rows
  const int cob = blockIdx.y;
  const int co0 = (MODE == 2) ? 0 : cob * 64;
  const int b = blockIdx.z;
  const int in_off = (MODE == 0) ? 0 : cob * CI;
  const float* inb = in + ((size_t)b*CI_TOT + in_off)*HWP;
  const uint32_t sbase = s2u(sm);

  float cacc[4][4][4];
  #pragma unroll
  for (int mm = 0; mm < 4; mm++)
    #pragma unroll
    for (int nn = 0; nn < 4; nn++)
      #pragma unroll
      for (int j = 0; j < 4; j++) cacc[mm][nn][j] = 0.f;

  for (int cb = 0; cb < CI/16; cb++) {
    __syncthreads();
    // ---- pixel tile [6 rows][66 cols][16 ci] fp16, 48B slot stride ----
    for (int i = tid; i < 792; i += 256) {
      int half = i & 1, slot = i >> 1;
      int r = slot / 66, c = slot - r*66;
      int y = rowblk*4 + r - 1, xx = c - 1;
      bool ok = ((unsigned)y < 64u) && ((unsigned)xx < 64u);
      const float* src = inb + (size_t)(cb*16 + half*8)*HWP + y*64 + xx;
      uint32_t hw[4];
      #pragma unroll
      for (int jj = 0; jj < 4; jj++) {
        float v0 = ok ? src[(size_t)(2*jj)*HWP]   : 0.f;
        float v1 = ok ? src[(size_t)(2*jj+1)*HWP] : 0.f;
        hw[jj] = (uint32_t)f16r(v0) | ((uint32_t)f16r(v1) << 16);
      }
      uint32_t boff = (uint32_t)slot*48 + half*16;
      *(uint4*)(sm + OP + boff) = make_uint4(hw[0],hw[1],hw[2],hw[3]);
    }
    // ---- weight tile [tap][64 co][16 ci re-paired] fp16 ----
    constexpr int PERM = TAPS*4;   // float4 per co-row for this ci-block
    for (int i = tid; i < 64*PERM; i += 256) {
      int m = i / PERM, q = i - m*PERM;
      size_t wb;
      if (MODE == 2) wb = ((size_t)m*CI_TOT + cob*CI + cb*16);
      else           wb = ((size_t)(co0 + m)*CI + cb*16);
      const float* wm = W + wb*TAPS;
      float4 v = *(const float4*)(wm + q*4);
      #pragma unroll
      for (int j = 0; j < 4; j++) {
        int e = q*4 + j;
        int ci = e / TAPS, t = e - ci*TAPS;
        int pos = ((ci & 7) >> 1)*4 + (ci >> 3)*2 + (ci & 1);
        uint32_t off = (uint32_t)((t*64 + m)*16 + pos)*2;
        *(uint16_t*)(sm + OW + off) = f16r((&v.x)[j]);
      }
    }
    __syncthreads();
    // ---- taps: shift pixel pointers, mma ----
    #pragma unroll 1
    for (int tap = 0; tap < TAPS; tap++) {
      int dy = (TAPS == 9) ? tap/3 - 1 : 0;
      int dx = (TAPS == 9) ? tap - (tap/3)*3 - 1 : 0;
      uint32_t ah[4][4];
      #pragma unroll
      for (int mm = 0; mm < 4; mm++) {
        int pxm = wy*64 + mm*16 + (lane & 15);
        int rr = (pxm >> 6) + 1 + dy;
        int cc = (pxm & 63) + 1 + dx;
        uint32_t boff = (uint32_t)(rr*66 + cc)*48 + ((lane >> 4) & 1)*16;
        ldmx4(ah[mm], sbase + OP + boff);
      }
      #pragma unroll
      for (int nn = 0; nn < 4; nn++) {
        int cof = wx*32 + nn*8 + g;
        uint32_t woff = (uint32_t)(tap*64 + cof)*32 + tq*8;
        uint2 bh = *(const uint2*)(sm + OW + woff);
        #pragma unroll
        for (int mm = 0; mm < 4; mm++) {
          mma_f16(cacc[mm][nn], ah[mm], bh.x, bh.y);
        }
      }
    }
  }
  // ---- epilogue: frags -> smem stage (stride 260 = conflict-free) -> gmem ----
  __syncthreads();
  float* osm = (float*)sm;
  #pragma unroll
  for (int mm = 0; mm < 4; mm++)
    #pragma unroll
    for (int nn = 0; nn < 4; nn++) {
      int px  = wy*64 + mm*16 + g;
      int col = wx*32 + nn*8 + tq*2;
      osm[(col  )*260 + px    ] = cacc[mm][nn][0];
      osm[(col+1)*260 + px    ] = cacc[mm][nn][1];
      osm[(col  )*260 + px + 8] = cacc[mm][nn][2];
      osm[(col+1)*260 + px + 8] = cacc[mm][nn][3];
    }
  __syncthreads();
  for (int i = tid; i < 16384; i += 256) {
    int col = i >> 8, px = i & 255;
    float v = osm[col*260 + px];
    int cg = co0 + col;
    if (EPI == 0) v += bias[cg];
    size_t obase;
    if (MODE == 2) obase = ((size_t)cob*BATCH*64 + (size_t)b*64 + cg)*HWP;
    else           obase = ((size_t)b*(gridDim.y*64) + cg)*HWP;
    out[obase + rowblk*256 + px] = v;
  }
  if (MODE == 1) {
    // per-channel partial sum over this CTA's 256 px (deterministic)
    int col = tid >> 2, quarter = tid & 3;
    const float* basep = osm + col*260 + quarter*64;
    float s = 0.f;
    #pragma unroll 16
    for (int p = 0; p < 64; p++) s += basep[p];
    s += __shfl_down_sync(0xffffffffu, s, 2);
    s += __shfl_down_sync(0xffffffffu, s, 1);
    if (quarter == 0)
      g_psum[((size_t)b*256 + cob*64 + col)*16 + rowblk] = s;
  }
}

// ---------------- K3: combine partials + BN + SiLU + 1x1 conv + softmax -------
// 4 threads per pixel (16-ci quarters); reads the 2 k2 partial slabs directly.
__global__ __launch_bounds__(256) void k3_kw(const float* __restrict__ Wkp2,
    const float* __restrict__ bkp2, const float* __restrict__ bkp1,
    const float* __restrict__ g1, const float* __restrict__ be1,
    const float* __restrict__ m1, const float* __restrict__ v1) {
  __shared__ float wst[64][40];      // transposed [ci][j], padded row
  __shared__ float bs[36];
  __shared__ float scs[64], shs[64];
  __shared__ float part[3][64][37];  // odd stride -> conflict-free
  int tid = threadIdx.x;
  for (int i = tid; i < 2304; i += 256) {
    int j = i >> 6, ci = i & 63;
    wst[ci][j] = Wkp2[i];
  }
  if (tid < 36) bs[tid] = bkp2[tid];
  if (tid >= 64 && tid < 128) {
    int c = tid - 64;
    float sc = g1[c]*rsqrtf(v1[c]+1e-5f);
    scs[c] = sc;
    shs[c] = be1[c] - m1[c]*sc + bkp1[c]*sc;
  }
  __syncthreads();
  int quart = tid >> 6;              // ci quarter
  int pl = tid & 63;
  int gp = blockIdx.x*64 + pl;       // 512 blocks x 64 px = 32768
  int b = gp >> 12, p = gp & 4095;
  const size_t SL = (size_t)BATCH*64*HWP;
  float acc[36];
  #pragma unroll
  for (int j=0;j<36;j++) acc[j]=0.f;
  const float* pb = g_part + (size_t)(b*64 + quart*16)*HWP + p;
  #pragma unroll 2
  for (int ci=0; ci<16; ci++) {
    size_t o = (size_t)ci*HWP;
    float v = pb[o] + pb[o+SL];
    int cg = quart*16 + ci;
    v = v*scs[cg] + shs[cg];
    float tv = v/(1.f+expf(-v));
    const float4* wp = (const float4*)&wst[cg][0];
    #pragma unroll
    for (int q=0;q<9;q++) {
      float4 w = wp[q];
      acc[4*q+0] += w.x*tv; acc[4*q+1] += w.y*tv;
      acc[4*q+2] += w.z*tv; acc[4*q+3] += w.w*tv;
    }
  }
  if (quart) {
    #pragma unroll
    for (int j=0;j<36;j++) part[quart-1][pl][j] = acc[j];
  }
  __syncthreads();
  if (!quart) {
    #pragma unroll
    for (int j=0;j<36;j++)
      acc[j] += part[0][pl][j] + part[1][pl][j] + part[2][pl][j] + bs[j];
    float ks[9];
    #pragma unroll
    for (int k=0;k<9;k++) ks[k]=0.f;
    float* kwp = g_kw + (size_t)gp*36;
    #pragma unroll
    for (int s=0;s<4;s++) {
      float m = acc[s*9];
      #pragma unroll
      for (int k=1;k<9;k++) m = fmaxf(m, acc[s*9+k]);
      float e[9]; float sum=0.f;
      #pragma unroll
      for (int k=0;k<9;k++){ e[k]=expf(acc[s*9+k]-m); sum+=e[k]; }
      float inv = 1.f/sum;
      #pragma unroll
      for (int k=0;k<9;k++){ float v=e[k]*inv; kwp[s*9+k]=v; ks[k]+=v; }
    }
    float* ksp = g_kwsum + (size_t)gp*9;
    #pragma unroll
    for (int k=0;k<9;k++) ksp[k]=ks[k];
  }
}

// ---------------- K3b: g map = 3x3 box correlation of kwsum -------------------
__global__ void k3b_gmap() {
  int gp = blockIdx.x*256 + threadIdx.x;
  int b = gp >> 12, p = gp & 4095;
  int i = p >> 6, j = p & 63;
  float s = 0.f;
  #pragma unroll
  for (int ih=0; ih<3; ih++)
    #pragma unroll
    for (int iw=0; iw<3; iw++) {
      int h = i + 1 - ih, w = j + 1 - iw;
      if ((unsigned)h < 64u && (unsigned)w < 64u)
        s += g_kwsum[(size_t)(b*4096 + h*64 + w)*9 + ih*3 + iw];
    }
  g_gmap[gp] = s;
}

// ---------------- K5b: pool x*gmap (main, after k3b) ---------------------------
__global__ __launch_bounds__(256) void k5b_pool(const float* __restrict__ x){
  int bc = blockIdx.x;
  int b = bc >> 8;
  const float* xp = x + (size_t)bc*HWP;
  const float* gp = g_gmap + (size_t)b*HWP;
  int tid = threadIdx.x;
  float s = 0.f;
  for (int i = tid; i < HWP; i += 256) s += xp[i]*gp[i];
  __shared__ float r[256];
  r[tid]=s; __syncthreads();
  for (int st=128; st>0; st>>=1) {
    if (tid < st) r[tid]+=r[tid+st];
    __syncthreads();
  }
  if (tid==0) g_pool_x[bc] = r[0];
}

// ---------------- K6: SE gate ---------------------------------------------------
__global__ __launch_bounds__(256) void k6_gate(const float* __restrict__ Wg1,
    const float* __restrict__ bg1, const float* __restrict__ Wg2,
    const float* __restrict__ bg2) {
  int b = blockIdx.x, tid = threadIdx.x;
  __shared__ float pl[256], hid[64];
  {
    const float4* ps = (const float4*)&g_psum[((size_t)b*256 + tid)*16];
    float se = 0.f;
    #pragma unroll
    for (int q = 0; q < 4; q++) {
      float4 v = ps[q];
      se += v.x + v.y + v.z + v.w;
    }
    pl[tid] = g_pool_x[b*256+tid]*(1.f/16384.f) + se*(1.f/4096.f);
  }
  __syncthreads();
  if (tid < 64) {
    float a = bg1[tid];
    for (int ci=0; ci<256; ci++) a += Wg1[tid*256+ci]*pl[ci];
    hid[tid] = a / (1.f + expf(-a));
  }
  __syncthreads();
  float a = bg2[tid];
  for (int j=0;j<64;j++) a += Wg2[tid*64+j]*hid[j];
  g_gate[b*256+tid] = 1.f/(1.f+expf(-a));
}

// ---------------- K7: reassembly + bilinear up + gate -> output ----------------
// Block: 4 h-rows x 64 cols x 16 channels (proven R11 shape).
__global__ __launch_bounds__(256, 2) void k7_fused(const float* __restrict__ x,
                                                   float* __restrict__ out) {
  extern __shared__ float sm7[];
  float* xs = sm7;                 // [16][6][66]
  float* es = sm7 + 16*6*66;       // [16][6][64]
  const int tid = threadIdx.x;
  const int c0 = blockIdx.x * 16;
  const int h0 = blockIdx.y * 4;
  const int b  = blockIdx.z;
  for (int i = tid; i < 16*6*66; i += 256) {
    int cc = i / 396, rem = i - cc*396;
    int rr = rem / 66, col = rem - rr*66 - 1;
    int y = h0 + rr - 1;
    float v = 0.f;
    if ((unsigned)y < 64u && (unsigned)col < 64u)
      v = x[((size_t)(b*CH)+c0+cc)*HWP + y*64 + col];
    xs[i] = v;
  }
  for (int i = tid; i < 16*6*64; i += 256) {
    int cc = i / 384, rem = i - cc*384;
    int rr = rem >> 6, col = rem & 63;
    int y = min(max(h0 + rr - 1, 0), 63);
    es[i] = g_enh[((size_t)(b*CH)+c0+cc)*HWP + y*64 + col];
  }
  __syncthreads();
  const int r = tid >> 6, col = tid & 63;
  const int h = h0 + r;
  float kp[36];
  {
    const float4* kq = (const float4*)(g_kw + ((size_t)(b*4096 + h*64 + col))*36);
    #pragma unroll
    for (int j = 0; j < 9; j++) {
      float4 v = kq[j];
      kp[4*j] = v.x; kp[4*j+1] = v.y; kp[4*j+2] = v.z; kp[4*j+3] = v.w;
    }
  }
  int base; float fw;
  if (col & 1) { base = (col - 1) >> 1; fw = 0.25f; }
  else         { base = (col >> 1) - 1; fw = 0.75f; }
  int cA0 = max(base, 0);
  int cB0 = base + 1;
  int cA1 = base + 32;
  int cB1 = min(base + 33, 63);
  float fw1 = 1.f - fw;
  #pragma unroll 1
  for (int cc = 0; cc < 16; cc++) {
    int c = c0 + cc;
    float gt = g_gate[b*256 + c];
    const float* xr = &xs[cc*396 + r*66 + col];
    float x00=xr[0],   x01=xr[1],   x02=xr[2];
    float x10=xr[66],  x11=xr[67],  x12=xr[68];
    float x20=xr[132], x21=xr[133], x22=xr[134];
    const float* er = &es[cc*384 + r*64];
    float rv[3][2];
    #pragma unroll
    for (int j = 0; j < 3; j++) {
      rv[j][0] = fw1*er[j*64 + cA0] + fw*er[j*64 + cB0];
      rv[j][1] = fw1*er[j*64 + cA1] + fw*er[j*64 + cB1];
    }
    float up[2][2];
    up[0][0] = 0.25f*rv[0][0] + 0.75f*rv[1][0];
    up[0][1] = 0.25f*rv[0][1] + 0.75f*rv[1][1];
    up[1][0] = 0.75f*rv[1][0] + 0.25f*rv[2][0];
    up[1][1] = 0.75f*rv[1][1] + 0.25f*rv[2][1];
    #pragma unroll
    for (int s = 0; s < 4; s++) {
      const float* kq = &kp[s*9];
      float ko = x00*kq[0]+x01*kq[1]+x02*kq[2]
               + x10*kq[3]+x11*kq[4]+x12*kq[5]
               + x20*kq[6]+x21*kq[7]+x22*kq[8];
      int di = s >> 1, dj = s & 1;
      size_t oidx = (size_t)(b*256 + c)*16384 + (size_t)(2*h+di)*128 + (size_t)(dj*64 + col);
      __stcs(&out[oidx], (ko + up[di][dj]) * gt);
    }
  }
}

// ---------------- launch --------------------------------------------------------
extern "C" void kernel_launch(void* const* d_in, const int* in_sizes, int n_in,
                              void* d_out, int out_size) {
  const float* x    = (const float*)d_in[0];
  const float* Wkc  = (const float*)d_in[1];
  const float* bkc  = (const float*)d_in[2];
  const float* Wkp1 = (const float*)d_in[3];
  const float* bkp1 = (const float*)d_in[4];
  const float* g1   = (const float*)d_in[5];
  const float* be1  = (const float*)d_in[6];
  const float* m1   = (const float*)d_in[7];
  const float* v1   = (const float*)d_in[8];
  const float* Wkp2 = (const float*)d_in[9];
  const float* bkp2 = (const float*)d_in[10];
  const float* Wdef = (const float*)d_in[11];
  const float* Wg1  = (const float*)d_in[12];
  const float* bg1  = (const float*)d_in[13];
  const float* Wg2  = (const float*)d_in[14];
  const float* bg2  = (const float*)d_in[15];
  float* out = (float*)d_out;

  float* comp = nullptr; float* part = nullptr; float* enh = nullptr;
  cudaGetSymbolAddress((void**)&comp, g_comp);
  cudaGetSymbolAddress((void**)&part, g_part);
  cudaGetSymbolAddress((void**)&enh,  g_enh);

  const int SM_CONV = 66560;
  const int SM_K7   = (16*6*66 + 16*6*64) * 4;   // 49920

  static cudaStream_t s2 = nullptr;
  static cudaEvent_t evFork = nullptr, evJoin = nullptr;
  if (s2 == nullptr) {
    cudaFuncSetAttribute((const void*)conv_mma<256,256,1,0,0>, cudaFuncAttributeMaxDynamicSharedMemorySize, SM_CONV);
    cudaFuncSetAttribute((const void*)conv_mma<64,128,9,2,2>,  cudaFuncAttributeMaxDynamicSharedMemorySize, SM_CONV);
    cudaFuncSetAttribute((const void*)conv_mma<64,256,9,2,1>,  cudaFuncAttributeMaxDynamicSharedMemorySize, SM_CONV);
    cudaFuncSetAttribute((const void*)k7_fused,                cudaFuncAttributeMaxDynamicSharedMemorySize, SM_K7);
    cudaStreamCreateWithFlags(&s2, cudaStreamNonBlocking);
    cudaEventCreateWithFlags(&evFork, cudaEventDisableTiming);
    cudaEventCreateWithFlags(&evJoin, cudaEventDisableTiming);
  }

  // ---- fork: k4 (with fused enh pool) on side stream; predictor chain on main
  cudaEventRecord(evFork, 0);
  cudaStreamWaitEvent(s2, evFork, 0);

  conv_mma<64,256,9,2,1><<<dim3(16,4,8), 256, SM_CONV, s2>>>(x, Wdef, enh, nullptr);

  conv_mma<256,256,1,0,0><<<dim3(16,2,8), 256, SM_CONV>>>(x, Wkc, comp, bkc);
  conv_mma<64,128,9,2,2><<<dim3(16,2,8), 256, SM_CONV>>>(comp, Wkp1, part, nullptr);
  k3_kw   <<<512, 256>>>(Wkp2, bkp2, bkp1, g1, be1, m1, v1);
  k3b_gmap<<<128, 256>>>();
  k5b_pool<<<2048, 256>>>(x);

  // ---- join: k6/k7 need enh + psum + pool_x ----
  cudaEventRecord(evJoin, s2);
  cudaStreamWaitEvent(0, evJoin, 0);

  k6_gate <<<8, 256>>>(Wg1, bg1, Wg2, bg2);
  k7_fused<<<dim3(16,16,8), 256, SM_K7>>>(x, out);
}

// round 15
// speedup vs baseline: 1.2836x; 1.0385x over previous
#include <cuda_runtime.h>
#include <cuda_fp16.h>
#include <cstdint>
#include <math.h>

#define BATCH 8
#define CH    256
#define HWP   4096   // 64*64

// ---------------- scratch (static device allocations; no cudaMalloc) ----------
__device__ __half g_comp [BATCH*128*HWP];   // fp16 (8.4 MB)
__device__ float  g_part [2*BATCH*64*HWP];  // k2 ci-split partials (16.8 MB)
__device__ float  g_kw   [BATCH*HWP*36];
__device__ float  g_kwsum[BATCH*HWP*9];
__device__ float  g_gmap [BATCH*HWP];
__device__ __half g_enh  [BATCH*CH*HWP];    // fp16 (16.8 MB)
__device__ float  g_psum [BATCH*CH*16];     // per-(b,c,rowblk) enh partial sums
__device__ float  g_pool_x[BATCH*CH];
__device__ float  g_gate  [BATCH*CH];

// ---------------- helpers ------------------------------------------------------
__device__ __forceinline__ uint32_t s2u(const void* p){
  uint32_t a; asm("{ .reg .u64 t; cvta.to.shared.u64 t, %1; cvt.u32.u64 %0, t; }"
                  : "=r"(a) : "l"(p)); return a;
}
__device__ __forceinline__ uint16_t f16r(float v){
  __half h = __float2half_rn(v);
  return __half_as_ushort(h);
}
__device__ __forceinline__ void ldmx4(uint32_t r[4], uint32_t addr){
  asm volatile("ldmatrix.sync.aligned.m8n8.x4.shared.b16 {%0,%1,%2,%3}, [%4];"
               : "=r"(r[0]), "=r"(r[1]), "=r"(r[2]), "=r"(r[3]) : "r"(addr));
}
__device__ __forceinline__ void mma_f16(float c[4], const uint32_t a[4],
                                        uint32_t b0, uint32_t b1){
  asm volatile("mma.sync.aligned.m16n8k16.row.col.f32.f16.f16.f32 "
               "{%0,%1,%2,%3},{%4,%5,%6,%7},{%8,%9},{%0,%1,%2,%3};"
               : "+f"(c[0]), "+f"(c[1]), "+f"(c[2]), "+f"(c[3])
               : "r"(a[0]), "r"(a[1]), "r"(a[2]), "r"(a[3]), "r"(b0), "r"(b1));
}

// ================= implicit-GEMM conv on HMMA fp16 (single-pass) ==============
// MODE 0: dense (k1). MODE 1: grouped (k4) + rowblk sums. MODE 2: ci-split (k2).
// EPI 0 = +bias, 2 = raw.  INH: input is fp16.  OUTH: output stored fp16.
template<int CI, int CI_TOT, int TAPS, int EPI, int MODE, int INH, int OUTH>
__global__ __launch_bounds__(256, 2) void conv_mma(
    const void* __restrict__ in, const float* __restrict__ W,
    void* __restrict__ out, const float* __restrict__ bias) {
  extern __shared__ char sm[];
  constexpr uint32_t OP = 0;                              // pixel plane 19008 B
  constexpr uint32_t OW = 6*66*48;                        // 19008

  const int tid = threadIdx.x;
  const int lane = tid & 31, wid = tid >> 5;
  const int wy = wid >> 1, wx = wid & 1;                  // 4 m-warps x 2 n-warps
  const int g = lane >> 2, tq = lane & 3;
  const int rowblk = blockIdx.x;                          // 4 image rows
  const int cob = blockIdx.y;
  const int co0 = (MODE == 2) ? 0 : cob * 64;
  const int b = blockIdx.z;
  const int in_off = (MODE == 0) ? 0 : cob * CI;
  const size_t in_base = ((size_t)b*CI_TOT + in_off)*HWP;
  const uint32_t sbase = s2u(sm);

  float cacc[4][4][4];
  #pragma unroll
  for (int mm = 0; mm < 4; mm++)
    #pragma unroll
    for (int nn = 0; nn < 4; nn++)
      #pragma unroll
      for (int j = 0; j < 4; j++) cacc[mm][nn][j] = 0.f;

  for (int cb = 0; cb < CI/16; cb++) {
    __syncthreads();
    // ---- pixel tile [6 rows][66 cols][16 ci] fp16, 48B slot stride ----
    for (int i = tid; i < 792; i += 256) {
      int half = i & 1, slot = i >> 1;
      int r = slot / 66, c = slot - r*66;
      int y = rowblk*4 + r - 1, xx = c - 1;
      bool ok = ((unsigned)y < 64u) && ((unsigned)xx < 64u);
      size_t soff = in_base + (size_t)(cb*16 + half*8)*HWP + y*64 + xx;
      uint32_t hw[4];
      if (INH) {
        const __half* src = (const __half*)in + soff;
        #pragma unroll
        for (int jj = 0; jj < 4; jj++) {
          uint16_t h0 = ok ? __half_as_ushort(src[(size_t)(2*jj)*HWP])   : (uint16_t)0;
          uint16_t h1 = ok ? __half_as_ushort(src[(size_t)(2*jj+1)*HWP]) : (uint16_t)0;
          hw[jj] = (uint32_t)h0 | ((uint32_t)h1 << 16);
        }
      } else {
        const float* src = (const float*)in + soff;
        #pragma unroll
        for (int jj = 0; jj < 4; jj++) {
          float v0 = ok ? src[(size_t)(2*jj)*HWP]   : 0.f;
          float v1 = ok ? src[(size_t)(2*jj+1)*HWP] : 0.f;
          hw[jj] = (uint32_t)f16r(v0) | ((uint32_t)f16r(v1) << 16);
        }
      }
      uint32_t boff = (uint32_t)slot*48 + half*16;
      *(uint4*)(sm + OP + boff) = make_uint4(hw[0],hw[1],hw[2],hw[3]);
    }
    // ---- weight tile [tap][64 co][16 ci re-paired] fp16 ----
    constexpr int PERM = TAPS*4;   // float4 per co-row for this ci-block
    for (int i = tid; i < 64*PERM; i += 256) {
      int m = i / PERM, q = i - m*PERM;
      size_t wb;
      if (MODE == 2) wb = ((size_t)m*CI_TOT + cob*CI + cb*16);
      else           wb = ((size_t)(co0 + m)*CI + cb*16);
      const float* wm = W + wb*TAPS;
      float4 v = *(const float4*)(wm + q*4);
      #pragma unroll
      for (int j = 0; j < 4; j++) {
        int e = q*4 + j;
        int ci = e / TAPS, t = e - ci*TAPS;
        int pos = ((ci & 7) >> 1)*4 + (ci >> 3)*2 + (ci & 1);
        uint32_t off = (uint32_t)((t*64 + m)*16 + pos)*2;
        *(uint16_t*)(sm + OW + off) = f16r((&v.x)[j]);
      }
    }
    __syncthreads();
    // ---- taps: shift pixel pointers, mma ----
    #pragma unroll 1
    for (int tap = 0; tap < TAPS; tap++) {
      int dy = (TAPS == 9) ? tap/3 - 1 : 0;
      int dx = (TAPS == 9) ? tap - (tap/3)*3 - 1 : 0;
      uint32_t ah[4][4];
      #pragma unroll
      for (int mm = 0; mm < 4; mm++) {
        int pxm = wy*64 + mm*16 + (lane & 15);
        int rr = (pxm >> 6) + 1 + dy;
        int cc = (pxm & 63) + 1 + dx;
        uint32_t boff = (uint32_t)(rr*66 + cc)*48 + ((lane >> 4) & 1)*16;
        ldmx4(ah[mm], sbase + OP + boff);
      }
      #pragma unroll
      for (int nn = 0; nn < 4; nn++) {
        int cof = wx*32 + nn*8 + g;
        uint32_t woff = (uint32_t)(tap*64 + cof)*32 + tq*8;
        uint2 bh = *(const uint2*)(sm + OW + woff);
        #pragma unroll
        for (int mm = 0; mm < 4; mm++) {
          mma_f16(cacc[mm][nn], ah[mm], bh.x, bh.y);
        }
      }
    }
  }
  // ---- epilogue: frags -> smem stage (stride 260 = conflict-free) -> gmem ----
  __syncthreads();
  float* osm = (float*)sm;
  #pragma unroll
  for (int mm = 0; mm < 4; mm++)
    #pragma unroll
    for (int nn = 0; nn < 4; nn++) {
      int px  = wy*64 + mm*16 + g;
      int col = wx*32 + nn*8 + tq*2;
      osm[(col  )*260 + px    ] = cacc[mm][nn][0];
      osm[(col+1)*260 + px    ] = cacc[mm][nn][1];
      osm[(col  )*260 + px + 8] = cacc[mm][nn][2];
      osm[(col+1)*260 + px + 8] = cacc[mm][nn][3];
    }
  __syncthreads();
  if (OUTH) {
    for (int i = tid; i < 8192; i += 256) {           // half2 stores
      int col = i >> 7, p2 = i & 127;
      float v0 = osm[col*260 + 2*p2];
      float v1 = osm[col*260 + 2*p2 + 1];
      int cg = co0 + col;
      if (EPI == 0) { v0 += bias[cg]; v1 += bias[cg]; }
      size_t obase = ((size_t)b*(gridDim.y*64) + cg)*HWP + rowblk*256;
      ((__half2*)((__half*)out + obase))[p2] = __floats2half2_rn(v0, v1);
    }
  } else {
    for (int i = tid; i < 16384; i += 256) {
      int col = i >> 8, px = i & 255;
      float v = osm[col*260 + px];
      int cg = co0 + col;
      if (EPI == 0) v += bias[cg];
      size_t obase;
      if (MODE == 2) obase = ((size_t)cob*BATCH*64 + (size_t)b*64 + cg)*HWP;
      else           obase = ((size_t)b*(gridDim.y*64) + cg)*HWP;
      ((float*)out)[obase + rowblk*256 + px] = v;
    }
  }
  if (MODE == 1) {
    // per-channel partial sum over this CTA's 256 px (deterministic, fp32 stage)
    int col = tid >> 2, quarter = tid & 3;
    const float* basep = osm + col*260 + quarter*64;
    float s = 0.f;
    #pragma unroll 16
    for (int p = 0; p < 64; p++) s += basep[p];
    s += __shfl_down_sync(0xffffffffu, s, 2);
    s += __shfl_down_sync(0xffffffffu, s, 1);
    if (quarter == 0)
      g_psum[((size_t)b*256 + cob*64 + col)*16 + rowblk] = s;
  }
}

// ---------------- K3: combine partials + BN + SiLU + 1x1 conv + softmax -------
__global__ __launch_bounds__(256) void k3_kw(const float* __restrict__ Wkp2,
    const float* __restrict__ bkp2, const float* __restrict__ bkp1,
    const float* __restrict__ g1, const float* __restrict__ be1,
    const float* __restrict__ m1, const float* __restrict__ v1) {
  __shared__ float wst[64][40];      // transposed [ci][j], padded row
  __shared__ float bs[36];
  __shared__ float scs[64], shs[64];
  __shared__ float part[3][64][37];  // odd stride -> conflict-free
  int tid = threadIdx.x;
  for (int i = tid; i < 2304; i += 256) {
    int j = i >> 6, ci = i & 63;
    wst[ci][j] = Wkp2[i];
  }
  if (tid < 36) bs[tid] = bkp2[tid];
  if (tid >= 64 && tid < 128) {
    int c = tid - 64;
    float sc = g1[c]*rsqrtf(v1[c]+1e-5f);
    scs[c] = sc;
    shs[c] = be1[c] - m1[c]*sc + bkp1[c]*sc;
  }
  __syncthreads();
  int quart = tid >> 6;              // ci quarter
  int pl = tid & 63;
  int gp = blockIdx.x*64 + pl;       // 512 blocks x 64 px = 32768
  int b = gp >> 12, p = gp & 4095;
  const size_t SL = (size_t)BATCH*64*HWP;
  float acc[36];
  #pragma unroll
  for (int j=0;j<36;j++) acc[j]=0.f;
  const float* pb = g_part + (size_t)(b*64 + quart*16)*HWP + p;
  #pragma unroll 2
  for (int ci=0; ci<16; ci++) {
    size_t o = (size_t)ci*HWP;
    float v = pb[o] + pb[o+SL];
    int cg = quart*16 + ci;
    v = v*scs[cg] + shs[cg];
    float tv = v/(1.f+expf(-v));
    const float4* wp = (const float4*)&wst[cg][0];
    #pragma unroll
    for (int q=0;q<9;q++) {
      float4 w = wp[q];
      acc[4*q+0] += w.x*tv; acc[4*q+1] += w.y*tv;
      acc[4*q+2] += w.z*tv; acc[4*q+3] += w.w*tv;
    }
  }
  if (quart) {
    #pragma unroll
    for (int j=0;j<36;j++) part[quart-1][pl][j] = acc[j];
  }
  __syncthreads();
  if (!quart) {
    #pragma unroll
    for (int j=0;j<36;j++)
      acc[j] += part[0][pl][j] + part[1][pl][j] + part[2][pl][j] + bs[j];
    float ks[9];
    #pragma unroll
    for (int k=0;k<9;k++) ks[k]=0.f;
    float* kwp = g_kw + (size_t)gp*36;
    #pragma unroll
    for (int s=0;s<4;s++) {
      float m = acc[s*9];
      #pragma unroll
      for (int k=1;k<9;k++) m = fmaxf(m, acc[s*9+k]);
      float e[9]; float sum=0.f;
      #pragma unroll
      for (int k=0;k<9;k++){ e[k]=expf(acc[s*9+k]-m); sum+=e[k]; }
      float inv = 1.f/sum;
      #pragma unroll
      for (int k=0;k<9;k++){ float v=e[k]*inv; kwp[s*9+k]=v; ks[k]+=v; }
    }
    float* ksp = g_kwsum + (size_t)gp*9;
    #pragma unroll
    for (int k=0;k<9;k++) ksp[k]=ks[k];
  }
}

// ---------------- K3b: g map = 3x3 box correlation of kwsum -------------------
__global__ void k3b_gmap() {
  int gp = blockIdx.x*256 + threadIdx.x;
  int b = gp >> 12, p = gp & 4095;
  int i = p >> 6, j = p & 63;
  float s = 0.f;
  #pragma unroll
  for (int ih=0; ih<3; ih++)
    #pragma unroll
    for (int iw=0; iw<3; iw++) {
      int h = i + 1 - ih, w = j + 1 - iw;
      if ((unsigned)h < 64u && (unsigned)w < 64u)
        s += g_kwsum[(size_t)(b*4096 + h*64 + w)*9 + ih*3 + iw];
    }
  g_gmap[gp] = s;
}

// ---------------- K5b: pool x*gmap (main, after k3b) ---------------------------
__global__ __launch_bounds__(256) void k5b_pool(const float* __restrict__ x){
  int bc = blockIdx.x;
  int b = bc >> 8;
  const float* xp = x + (size_t)bc*HWP;
  const float* gp = g_gmap + (size_t)b*HWP;
  int tid = threadIdx.x;
  float s = 0.f;
  for (int i = tid; i < HWP; i += 256) s += xp[i]*gp[i];
  __shared__ float r[256];
  r[tid]=s; __syncthreads();
  for (int st=128; st>0; st>>=1) {
    if (tid < st) r[tid]+=r[tid+st];
    __syncthreads();
  }
  if (tid==0) g_pool_x[bc] = r[0];
}

// ---------------- K6: SE gate ---------------------------------------------------
__global__ __launch_bounds__(256) void k6_gate(const float* __restrict__ Wg1,
    const float* __restrict__ bg1, const float* __restrict__ Wg2,
    const float* __restrict__ bg2) {
  int b = blockIdx.x, tid = threadIdx.x;
  __shared__ float pl[256], hid[64];
  {
    const float4* ps = (const float4*)&g_psum[((size_t)b*256 + tid)*16];
    float se = 0.f;
    #pragma unroll
    for (int q = 0; q < 4; q++) {
      float4 v = ps[q];
      se += v.x + v.y + v.z + v.w;
    }
    pl[tid] = g_pool_x[b*256+tid]*(1.f/16384.f) + se*(1.f/4096.f);
  }
  __syncthreads();
  if (tid < 64) {
    float a = bg1[tid];
    for (int ci=0; ci<256; ci++) a += Wg1[tid*256+ci]*pl[ci];
    hid[tid] = a / (1.f + expf(-a));
  }
  __syncthreads();
  float a = bg2[tid];
  for (int j=0;j<64;j++) a += Wg2[tid*64+j]*hid[j];
  g_gate[b*256+tid] = 1.f/(1.f+expf(-a));
}

// ---------------- K7: reassembly + bilinear up + gate -> output ----------------
// Block: 4 h-rows x 64 cols x 16 channels (proven R11 shape); enh read fp16.
__global__ __launch_bounds__(256, 2) void k7_fused(const float* __restrict__ x,
                                                   float* __restrict__ out) {
  extern __shared__ float sm7[];
  float* xs = sm7;                 // [16][6][66]
  float* es = sm7 + 16*6*66;       // [16][6][64]
  const int tid = threadIdx.x;
  const int c0 = blockIdx.x * 16;
  const int h0 = blockIdx.y * 4;
  const int b  = blockIdx.z;
  for (int i = tid; i < 16*6*66; i += 256) {
    int cc = i / 396, rem = i - cc*396;
    int rr = rem / 66, col = rem - rr*66 - 1;
    int y = h0 + rr - 1;
    float v = 0.f;
    if ((unsigned)y < 64u && (unsigned)col < 64u)
      v = x[((size_t)(b*CH)+c0+cc)*HWP + y*64 + col];
    xs[i] = v;
  }
  for (int i = tid; i < 16*6*64; i += 256) {
    int cc = i / 384, rem = i - cc*384;
    int rr = rem >> 6, col = rem & 63;
    int y = min(max(h0 + rr - 1, 0), 63);
    es[i] = __half2float(g_enh[((size_t)(b*CH)+c0+cc)*HWP + y*64 + col]);
  }
  __syncthreads();
  const int r = tid >> 6, col = tid & 63;
  const int h = h0 + r;
  float kp[36];
  {
    const float4* kq = (const float4*)(g_kw + ((size_t)(b*4096 + h*64 + col))*36);
    #pragma unroll
    for (int j = 0; j < 9; j++) {
      float4 v = kq[j];
      kp[4*j] = v.x; kp[4*j+1] = v.y; kp[4*j+2] = v.z; kp[4*j+3] = v.w;
    }
  }
  int base; float fw;
  if (col & 1) { base = (col - 1) >> 1; fw = 0.25f; }
  else         { base = (col >> 1) - 1; fw = 0.75f; }
  int cA0 = max(base, 0);
  int cB0 = base + 1;
  int cA1 = base + 32;
  int cB1 = min(base + 33, 63);
  float fw1 = 1.f - fw;
  #pragma unroll 1
  for (int cc = 0; cc < 16; cc++) {
    int c = c0 + cc;
    float gt = g_gate[b*256 + c];
    const float* xr = &xs[cc*396 + r*66 + col];
    float x00=xr[0],   x01=xr[1],   x02=xr[2];
    float x10=xr[66],  x11=xr[67],  x12=xr[68];
    float x20=xr[132], x21=xr[133], x22=xr[134];
    const float* er = &es[cc*384 + r*64];
    float rv[3][2];
    #pragma unroll
    for (int j = 0; j < 3; j++) {
      rv[j][0] = fw1*er[j*64 + cA0] + fw*er[j*64 + cB0];
      rv[j][1] = fw1*er[j*64 + cA1] + fw*er[j*64 + cB1];
    }
    float up[2][2];
    up[0][0] = 0.25f*rv[0][0] + 0.75f*rv[1][0];
    up[0][1] = 0.25f*rv[0][1] + 0.75f*rv[1][1];
    up[1][0] = 0.75f*rv[1][0] + 0.25f*rv[2][0];
    up[1][1] = 0.75f*rv[1][1] + 0.25f*rv[2][1];
    #pragma unroll
    for (int s = 0; s < 4; s++) {
      const float* kq = &kp[s*9];
      float ko = x00*kq[0]+x01*kq[1]+x02*kq[2]
               + x10*kq[3]+x11*kq[4]+x12*kq[5]
               + x20*kq[6]+x21*kq[7]+x22*kq[8];
      int di = s >> 1, dj = s & 1;
      size_t oidx = (size_t)(b*256 + c)*16384 + (size_t)(2*h+di)*128 + (size_t)(dj*64 + col);
      __stcs(&out[oidx], (ko + up[di][dj]) * gt);
    }
  }
}

// ---------------- launch --------------------------------------------------------
extern "C" void kernel_launch(void* const* d_in, const int* in_sizes, int n_in,
                              void* d_out, int out_size) {
  const float* x    = (const float*)d_in[0];
  const float* Wkc  = (const float*)d_in[1];
  const float* bkc  = (const float*)d_in[2];
  const float* Wkp1 = (const float*)d_in[3];
  const float* bkp1 = (const float*)d_in[4];
  const float* g1   = (const float*)d_in[5];
  const float* be1  = (const float*)d_in[6];
  const float* m1   = (const float*)d_in[7];
  const float* v1   = (const float*)d_in[8];
  const float* Wkp2 = (const float*)d_in[9];
  const float* bkp2 = (const float*)d_in[10];
  const float* Wdef = (const float*)d_in[11];
  const float* Wg1  = (const float*)d_in[12];
  const float* bg1  = (const float*)d_in[13];
  const float* Wg2  = (const float*)d_in[14];
  const float* bg2  = (const float*)d_in[15];
  float* out = (float*)d_out;

  void* comp = nullptr; void* part = nullptr; void* enh = nullptr;
  cudaGetSymbolAddress(&comp, g_comp);
  cudaGetSymbolAddress(&part, g_part);
  cudaGetSymbolAddress(&enh,  g_enh);

  const int SM_CONV = 66560;
  const int SM_K7   = (16*6*66 + 16*6*64) * 4;   // 49920

  static cudaStream_t s2 = nullptr;
  static cudaEvent_t evFork = nullptr, evJoin = nullptr;
  if (s2 == nullptr) {
    cudaFuncSetAttribute((const void*)conv_mma<256,256,1,0,0,0,1>, cudaFuncAttributeMaxDynamicSharedMemorySize, SM_CONV);
    cudaFuncSetAttribute((const void*)conv_mma<64,128,9,2,2,1,0>,  cudaFuncAttributeMaxDynamicSharedMemorySize, SM_CONV);
    cudaFuncSetAttribute((const void*)conv_mma<64,256,9,2,1,0,1>,  cudaFuncAttributeMaxDynamicSharedMemorySize, SM_CONV);
    cudaFuncSetAttribute((const void*)k7_fused,                    cudaFuncAttributeMaxDynamicSharedMemorySize, SM_K7);
    cudaStreamCreateWithFlags(&s2, cudaStreamNonBlocking);
    cudaEventCreateWithFlags(&evFork, cudaEventDisableTiming);
    cudaEventCreateWithFlags(&evJoin, cudaEventDisableTiming);
  }

  // ---- fork: k4 (with fused enh pool) on side stream; predictor chain on main
  cudaEventRecord(evFork, 0);
  cudaStreamWaitEvent(s2, evFork, 0);

  conv_mma<64,256,9,2,1,0,1><<<dim3(16,4,8), 256, SM_CONV, s2>>>(x, Wdef, enh, nullptr);

  conv_mma<256,256,1,0,0,0,1><<<dim3(16,2,8), 256, SM_CONV>>>(x, Wkc, comp, bkc);
  conv_mma<64,128,9,2,2,1,0><<<dim3(16,2,8), 256, SM_CONV>>>(comp, Wkp1, part, nullptr);
  k3_kw   <<<512, 256>>>(Wkp2, bkp2, bkp1, g1, be1, m1, v1);
  k3b_gmap<<<128, 256>>>();
  k5b_pool<<<2048, 256>>>(x);

  // ---- join: k6/k7 need enh + psum + pool_x ----
  cudaEventRecord(evJoin, s2);
  cudaStreamWaitEvent(0, evJoin, 0);

  k6_gate <<<8, 256>>>(Wg1, bg1, Wg2, bg2);
  k7_fused<<<dim3(16,16,8), 256, SM_K7>>>(x, out);
}

// round 16
// speedup vs baseline: 1.2942x; 1.0083x over previous
#include <cuda_runtime.h>
#include <cuda_fp16.h>
#include <cstdint>
#include <math.h>

#define BATCH 8
#define CH    256
#define HWP   4096   // 64*64

// ---------------- scratch (static device allocations; no cudaMalloc) ----------
__device__ __half g_xh   [BATCH*CH*HWP];    // fp16 copy of x (16.8 MB)
__device__ __half g_comp [BATCH*128*HWP];   // fp16 (8.4 MB)
__device__ float  g_part [2*BATCH*64*HWP];  // k2 ci-split partials (16.8 MB)
__device__ float  g_kw   [BATCH*HWP*36];
__device__ float  g_kwsum[BATCH*HWP*9];
__device__ float  g_gmap [BATCH*HWP];
__device__ __half g_enh  [BATCH*CH*HWP];    // fp16 (16.8 MB)
__device__ float  g_psum [BATCH*CH*16];     // per-(b,c,rowblk) enh partial sums
__device__ float  g_pool_x[BATCH*CH];
__device__ float  g_gate  [BATCH*CH];

// ---------------- helpers ------------------------------------------------------
__device__ __forceinline__ uint32_t s2u(const void* p){
  uint32_t a; asm("{ .reg .u64 t; cvta.to.shared.u64 t, %1; cvt.u32.u64 %0, t; }"
                  : "=r"(a) : "l"(p)); return a;
}
__device__ __forceinline__ uint16_t f16r(float v){
  __half h = __float2half_rn(v);
  return __half_as_ushort(h);
}
__device__ __forceinline__ void ldmx4(uint32_t r[4], uint32_t addr){
  asm volatile("ldmatrix.sync.aligned.m8n8.x4.shared.b16 {%0,%1,%2,%3}, [%4];"
               : "=r"(r[0]), "=r"(r[1]), "=r"(r[2]), "=r"(r[3]) : "r"(addr));
}
__device__ __forceinline__ void mma_f16(float c[4], const uint32_t a[4],
                                        uint32_t b0, uint32_t b1){
  asm volatile("mma.sync.aligned.m16n8k16.row.col.f32.f16.f16.f32 "
               "{%0,%1,%2,%3},{%4,%5,%6,%7},{%8,%9},{%0,%1,%2,%3};"
               : "+f"(c[0]), "+f"(c[1]), "+f"(c[2]), "+f"(c[3])
               : "r"(a[0]), "r"(a[1]), "r"(a[2]), "r"(a[3]), "r"(b0), "r"(b1));
}

// ================= implicit-GEMM conv on HMMA fp16 (single-pass) ==============
// MODE 0: dense (k1). MODE 1: grouped (k4) + rowblk sums. MODE 2: ci-split (k2).
// EPI 0 = +bias, 2 = raw.  INH: input is fp16.  OUTH: output stored fp16.
// WXH: while building pixel tiles (fp32 input), also emit fp16 copy to g_xh
//      (only from cob==0 blocks; duplicate halo stores write identical values).
template<int CI, int CI_TOT, int TAPS, int EPI, int MODE, int INH, int OUTH, int WXH>
__global__ __launch_bounds__(256, 2) void conv_mma(
    const void* __restrict__ in, const float* __restrict__ W,
    void* __restrict__ out, const float* __restrict__ bias) {
  extern __shared__ char sm[];
  constexpr uint32_t OP = 0;                              // pixel plane 19008 B
  constexpr uint32_t OW = 6*66*48;                        // 19008

  const int tid = threadIdx.x;
  const int lane = tid & 31, wid = tid >> 5;
  const int wy = wid >> 1, wx = wid & 1;                  // 4 m-warps x 2 n-warps
  const int g = lane >> 2, tq = lane & 3;
  const int rowblk = blockIdx.x;                          // 4 image rows
  const int cob = blockIdx.y;
  const int co0 = (MODE == 2) ? 0 : cob * 64;
  const int b = blockIdx.z;
  const int in_off = (MODE == 0) ? 0 : cob * CI;
  const size_t in_base = ((size_t)b*CI_TOT + in_off)*HWP;
  const uint32_t sbase = s2u(sm);

  float cacc[4][4][4];
  #pragma unroll
  for (int mm = 0; mm < 4; mm++)
    #pragma unroll
    for (int nn = 0; nn < 4; nn++)
      #pragma unroll
      for (int j = 0; j < 4; j++) cacc[mm][nn][j] = 0.f;

  for (int cb = 0; cb < CI/16; cb++) {
    __syncthreads();
    // ---- pixel tile [6 rows][66 cols][16 ci] fp16, 48B slot stride ----
    for (int i = tid; i < 792; i += 256) {
      int half = i & 1, slot = i >> 1;
      int r = slot / 66, c = slot - r*66;
      int y = rowblk*4 + r - 1, xx = c - 1;
      bool ok = ((unsigned)y < 64u) && ((unsigned)xx < 64u);
      size_t soff = in_base + (size_t)(cb*16 + half*8)*HWP + y*64 + xx;
      uint32_t hw[4];
      if (INH) {
        const __half* src = (const __half*)in + soff;
        #pragma unroll
        for (int jj = 0; jj < 4; jj++) {
          uint16_t h0 = ok ? __half_as_ushort(src[(size_t)(2*jj)*HWP])   : (uint16_t)0;
          uint16_t h1 = ok ? __half_as_ushort(src[(size_t)(2*jj+1)*HWP]) : (uint16_t)0;
          hw[jj] = (uint32_t)h0 | ((uint32_t)h1 << 16);
        }
      } else {
        const float* src = (const float*)in + soff;
        #pragma unroll
        for (int jj = 0; jj < 4; jj++) {
          float v0 = ok ? src[(size_t)(2*jj)*HWP]   : 0.f;
          float v1 = ok ? src[(size_t)(2*jj+1)*HWP] : 0.f;
          uint16_t u0 = f16r(v0), u1 = f16r(v1);
          hw[jj] = (uint32_t)u0 | ((uint32_t)u1 << 16);
          if (WXH && ok && cob == 0) {
            *(uint16_t*)&g_xh[soff + (size_t)(2*jj)*HWP]   = u0;
            *(uint16_t*)&g_xh[soff + (size_t)(2*jj+1)*HWP] = u1;
          }
        }
      }
      uint32_t boff = (uint32_t)slot*48 + half*16;
      *(uint4*)(sm + OP + boff) = make_uint4(hw[0],hw[1],hw[2],hw[3]);
    }
    // ---- weight tile [tap][64 co][16 ci re-paired] fp16 ----
    constexpr int PERM = TAPS*4;   // float4 per co-row for this ci-block
    for (int i = tid; i < 64*PERM; i += 256) {
      int m = i / PERM, q = i - m*PERM;
      size_t wb;
      if (MODE == 2) wb = ((size_t)m*CI_TOT + cob*CI + cb*16);
      else           wb = ((size_t)(co0 + m)*CI + cb*16);
      const float* wm = W + wb*TAPS;
      float4 v = *(const float4*)(wm + q*4);
      #pragma unroll
      for (int j = 0; j < 4; j++) {
        int e = q*4 + j;
        int ci = e / TAPS, t = e - ci*TAPS;
        int pos = ((ci & 7) >> 1)*4 + (ci >> 3)*2 + (ci & 1);
        uint32_t off = (uint32_t)((t*64 + m)*16 + pos)*2;
        *(uint16_t*)(sm + OW + off) = f16r((&v.x)[j]);
      }
    }
    __syncthreads();
    // ---- taps: shift pixel pointers, mma ----
    #pragma unroll 1
    for (int tap = 0; tap < TAPS; tap++) {
      int dy = (TAPS == 9) ? tap/3 - 1 : 0;
      int dx = (TAPS == 9) ? tap - (tap/3)*3 - 1 : 0;
      uint32_t ah[4][4];
      #pragma unroll
      for (int mm = 0; mm < 4; mm++) {
        int pxm = wy*64 + mm*16 + (lane & 15);
        int rr = (pxm >> 6) + 1 + dy;
        int cc = (pxm & 63) + 1 + dx;
        uint32_t boff = (uint32_t)(rr*66 + cc)*48 + ((lane >> 4) & 1)*16;
        ldmx4(ah[mm], sbase + OP + boff);
      }
      #pragma unroll
      for (int nn = 0; nn < 4; nn++) {
        int cof = wx*32 + nn*8 + g;
        uint32_t woff = (uint32_t)(tap*64 + cof)*32 + tq*8;
        uint2 bh = *(const uint2*)(sm + OW + woff);
        #pragma unroll
        for (int mm = 0; mm < 4; mm++) {
          mma_f16(cacc[mm][nn], ah[mm], bh.x, bh.y);
        }
      }
    }
  }
  // ---- epilogue: frags -> smem stage (stride 260 = conflict-free) -> gmem ----
  __syncthreads();
  float* osm = (float*)sm;
  #pragma unroll
  for (int mm = 0; mm < 4; mm++)
    #pragma unroll
    for (int nn = 0; nn < 4; nn++) {
      int px  = wy*64 + mm*16 + g;
      int col = wx*32 + nn*8 + tq*2;
      osm[(col  )*260 + px    ] = cacc[mm][nn][0];
      osm[(col+1)*260 + px    ] = cacc[mm][nn][1];
      osm[(col  )*260 + px + 8] = cacc[mm][nn][2];
      osm[(col+1)*260 + px + 8] = cacc[mm][nn][3];
    }
  __syncthreads();
  if (OUTH) {
    for (int i = tid; i < 8192; i += 256) {           // half2 stores
      int col = i >> 7, p2 = i & 127;
      float v0 = osm[col*260 + 2*p2];
      float v1 = osm[col*260 + 2*p2 + 1];
      int cg = co0 + col;
      if (EPI == 0) { v0 += bias[cg]; v1 += bias[cg]; }
      size_t obase = ((size_t)b*(gridDim.y*64) + cg)*HWP + rowblk*256;
      ((__half2*)((__half*)out + obase))[p2] = __floats2half2_rn(v0, v1);
    }
  } else {
    for (int i = tid; i < 16384; i += 256) {
      int col = i >> 8, px = i & 255;
      float v = osm[col*260 + px];
      int cg = co0 + col;
      if (EPI == 0) v += bias[cg];
      size_t obase;
      if (MODE == 2) obase = ((size_t)cob*BATCH*64 + (size_t)b*64 + cg)*HWP;
      else           obase = ((size_t)b*(gridDim.y*64) + cg)*HWP;
      ((float*)out)[obase + rowblk*256 + px] = v;
    }
  }
  if (MODE == 1) {
    // per-channel partial sum over this CTA's 256 px (deterministic, fp32 stage)
    int col = tid >> 2, quarter = tid & 3;
    const float* basep = osm + col*260 + quarter*64;
    float s = 0.f;
    #pragma unroll 16
    for (int p = 0; p < 64; p++) s += basep[p];
    s += __shfl_down_sync(0xffffffffu, s, 2);
    s += __shfl_down_sync(0xffffffffu, s, 1);
    if (quarter == 0)
      g_psum[((size_t)b*256 + cob*64 + col)*16 + rowblk] = s;
  }
}

// ---------------- K3: combine partials + BN + SiLU + 1x1 conv + softmax -------
__global__ __launch_bounds__(256) void k3_kw(const float* __restrict__ Wkp2,
    const float* __restrict__ bkp2, const float* __restrict__ bkp1,
    const float* __restrict__ g1, const float* __restrict__ be1,
    const float* __restrict__ m1, const float* __restrict__ v1) {
  __shared__ float wst[64][40];      // transposed [ci][j], padded row
  __shared__ float bs[36];
  __shared__ float scs[64], shs[64];
  __shared__ float part[3][64][37];  // odd stride -> conflict-free
  int tid = threadIdx.x;
  for (int i = tid; i < 2304; i += 256) {
    int j = i >> 6, ci = i & 63;
    wst[ci][j] = Wkp2[i];
  }
  if (tid < 36) bs[tid] = bkp2[tid];
  if (tid >= 64 && tid < 128) {
    int c = tid - 64;
    float sc = g1[c]*rsqrtf(v1[c]+1e-5f);
    scs[c] = sc;
    shs[c] = be1[c] - m1[c]*sc + bkp1[c]*sc;
  }
  __syncthreads();
  int quart = tid >> 6;              // ci quarter
  int pl = tid & 63;
  int gp = blockIdx.x*64 + pl;       // 512 blocks x 64 px = 32768
  int b = gp >> 12, p = gp & 4095;
  const size_t SL = (size_t)BATCH*64*HWP;
  float acc[36];
  #pragma unroll
  for (int j=0;j<36;j++) acc[j]=0.f;
  const float* pb = g_part + (size_t)(b*64 + quart*16)*HWP + p;
  #pragma unroll 2
  for (int ci=0; ci<16; ci++) {
    size_t o = (size_t)ci*HWP;
    float v = pb[o] + pb[o+SL];
    int cg = quart*16 + ci;
    v = v*scs[cg] + shs[cg];
    float tv = v/(1.f+expf(-v));
    const float4* wp = (const float4*)&wst[cg][0];
    #pragma unroll
    for (int q=0;q<9;q++) {
      float4 w = wp[q];
      acc[4*q+0] += w.x*tv; acc[4*q+1] += w.y*tv;
      acc[4*q+2] += w.z*tv; acc[4*q+3] += w.w*tv;
    }
  }
  if (quart) {
    #pragma unroll
    for (int j=0;j<36;j++) part[quart-1][pl][j] = acc[j];
  }
  __syncthreads();
  if (!quart) {
    #pragma unroll
    for (int j=0;j<36;j++)
      acc[j] += part[0][pl][j] + part[1][pl][j] + part[2][pl][j] + bs[j];
    float ks[9];
    #pragma unroll
    for (int k=0;k<9;k++) ks[k]=0.f;
    float* kwp = g_kw + (size_t)gp*36;
    #pragma unroll
    for (int s=0;s<4;s++) {
      float m = acc[s*9];
      #pragma unroll
      for (int k=1;k<9;k++) m = fmaxf(m, acc[s*9+k]);
      float e[9]; float sum=0.f;
      #pragma unroll
      for (int k=0;k<9;k++){ e[k]=expf(acc[s*9+k]-m); sum+=e[k]; }
      float inv = 1.f/sum;
      #pragma unroll
      for (int k=0;k<9;k++){ float v=e[k]*inv; kwp[s*9+k]=v; ks[k]+=v; }
    }
    float* ksp = g_kwsum + (size_t)gp*9;
    #pragma unroll
    for (int k=0;k<9;k++) ksp[k]=ks[k];
  }
}

// ---------------- K3b: g map = 3x3 box correlation of kwsum -------------------
__global__ void k3b_gmap() {
  int gp = blockIdx.x*256 + threadIdx.x;
  int b = gp >> 12, p = gp & 4095;
  int i = p >> 6, j = p & 63;
  float s = 0.f;
  #pragma unroll
  for (int ih=0; ih<3; ih++)
    #pragma unroll
    for (int iw=0; iw<3; iw++) {
      int h = i + 1 - ih, w = j + 1 - iw;
      if ((unsigned)h < 64u && (unsigned)w < 64u)
        s += g_kwsum[(size_t)(b*4096 + h*64 + w)*9 + ih*3 + iw];
    }
  g_gmap[gp] = s;
}

// ---------------- K5b: pool x*gmap (fp16 x copy) -------------------------------
__global__ __launch_bounds__(256) void k5b_pool(){
  int bc = blockIdx.x;
  int b = bc >> 8;
  const __half* xp = g_xh + (size_t)bc*HWP;
  const float* gp = g_gmap + (size_t)b*HWP;
  int tid = threadIdx.x;
  float s = 0.f;
  for (int i = tid; i < HWP; i += 256) s += __half2float(xp[i])*gp[i];
  __shared__ float r[256];
  r[tid]=s; __syncthreads();
  for (int st=128; st>0; st>>=1) {
    if (tid < st) r[tid]+=r[tid+st];
    __syncthreads();
  }
  if (tid==0) g_pool_x[bc] = r[0];
}

// ---------------- K6: SE gate ---------------------------------------------------
__global__ __launch_bounds__(256) void k6_gate(const float* __restrict__ Wg1,
    const float* __restrict__ bg1, const float* __restrict__ Wg2,
    const float* __restrict__ bg2) {
  int b = blockIdx.x, tid = threadIdx.x;
  __shared__ float pl[256], hid[64];
  {
    const float4* ps = (const float4*)&g_psum[((size_t)b*256 + tid)*16];
    float se = 0.f;
    #pragma unroll
    for (int q = 0; q < 4; q++) {
      float4 v = ps[q];
      se += v.x + v.y + v.z + v.w;
    }
    pl[tid] = g_pool_x[b*256+tid]*(1.f/16384.f) + se*(1.f/4096.f);
  }
  __syncthreads();
  if (tid < 64) {
    float a = bg1[tid];
    for (int ci=0; ci<256; ci++) a += Wg1[tid*256+ci]*pl[ci];
    hid[tid] = a / (1.f + expf(-a));
  }
  __syncthreads();
  float a = bg2[tid];
  for (int j=0;j<64;j++) a += Wg2[tid*64+j]*hid[j];
  g_gate[b*256+tid] = 1.f/(1.f+expf(-a));
}

// ---------------- K7: reassembly + bilinear up + gate -> output ----------------
// Block: 4 h-rows x 64 cols x 16 channels; x and enh read fp16.
__global__ __launch_bounds__(256, 2) void k7_fused(float* __restrict__ out) {
  extern __shared__ float sm7[];
  float* xs = sm7;                 // [16][6][66]
  float* es = sm7 + 16*6*66;       // [16][6][64]
  const int tid = threadIdx.x;
  const int c0 = blockIdx.x * 16;
  const int h0 = blockIdx.y * 4;
  const int b  = blockIdx.z;
  for (int i = tid; i < 16*6*66; i += 256) {
    int cc = i / 396, rem = i - cc*396;
    int rr = rem / 66, col = rem - rr*66 - 1;
    int y = h0 + rr - 1;
    float v = 0.f;
    if ((unsigned)y < 64u && (unsigned)col < 64u)
      v = __half2float(g_xh[((size_t)(b*CH)+c0+cc)*HWP + y*64 + col]);
    xs[i] = v;
  }
  for (int i = tid; i < 16*6*64; i += 256) {
    int cc = i / 384, rem = i - cc*384;
    int rr = rem >> 6, col = rem & 63;
    int y = min(max(h0 + rr - 1, 0), 63);
    es[i] = __half2float(g_enh[((size_t)(b*CH)+c0+cc)*HWP + y*64 + col]);
  }
  __syncthreads();
  const int r = tid >> 6, col = tid & 63;
  const int h = h0 + r;
  float kp[36];
  {
    const float4* kq = (const float4*)(g_kw + ((size_t)(b*4096 + h*64 + col))*36);
    #pragma unroll
    for (int j = 0; j < 9; j++) {
      float4 v = kq[j];
      kp[4*j] = v.x; kp[4*j+1] = v.y; kp[4*j+2] = v.z; kp[4*j+3] = v.w;
    }
  }
  int base; float fw;
  if (col & 1) { base = (col - 1) >> 1; fw = 0.25f; }
  else         { base = (col >> 1) - 1; fw = 0.75f; }
  int cA0 = max(base, 0);
  int cB0 = base + 1;
  int cA1 = base + 32;
  int cB1 = min(base + 33, 63);
  float fw1 = 1.f - fw;
  #pragma unroll 1
  for (int cc = 0; cc < 16; cc++) {
    int c = c0 + cc;
    float gt = g_gate[b*256 + c];
    const float* xr = &xs[cc*396 + r*66 + col];
    float x00=xr[0],   x01=xr[1],   x02=xr[2];
    float x10=xr[66],  x11=xr[67],  x12=xr[68];
    float x20=xr[132], x21=xr[133], x22=xr[134];
    const float* er = &es[cc*384 + r*64];
    float rv[3][2];
    #pragma unroll
    for (int j = 0; j < 3; j++) {
      rv[j][0] = fw1*er[j*64 + cA0] + fw*er[j*64 + cB0];
      rv[j][1] = fw1*er[j*64 + cA1] + fw*er[j*64 + cB1];
    }
    float up[2][2];
    up[0][0] = 0.25f*rv[0][0] + 0.75f*rv[1][0];
    up[0][1] = 0.25f*rv[0][1] + 0.75f*rv[1][1];
    up[1][0] = 0.75f*rv[1][0] + 0.25f*rv[2][0];
    up[1][1] = 0.75f*rv[1][1] + 0.25f*rv[2][1];
    #pragma unroll
    for (int s = 0; s < 4; s++) {
      const float* kq = &kp[s*9];
      float ko = x00*kq[0]+x01*kq[1]+x02*kq[2]
               + x10*kq[3]+x11*kq[4]+x12*kq[5]
               + x20*kq[6]+x21*kq[7]+x22*kq[8];
      int di = s >> 1, dj = s & 1;
      size_t oidx = (size_t)(b*256 + c)*16384 + (size_t)(2*h+di)*128 + (size_t)(dj*64 + col);
      __stcs(&out[oidx], (ko + up[di][dj]) * gt);
    }
  }
}

// ---------------- launch --------------------------------------------------------
extern "C" void kernel_launch(void* const* d_in, const int* in_sizes, int n_in,
                              void* d_out, int out_size) {
  const float* x    = (const float*)d_in[0];
  const float* Wkc  = (const float*)d_in[1];
  const float* bkc  = (const float*)d_in[2];
  const float* Wkp1 = (const float*)d_in[3];
  const float* bkp1 = (const float*)d_in[4];
  const float* g1   = (const float*)d_in[5];
  const float* be1  = (const float*)d_in[6];
  const float* m1   = (const float*)d_in[7];
  const float* v1   = (const float*)d_in[8];
  const float* Wkp2 = (const float*)d_in[9];
  const float* bkp2 = (const float*)d_in[10];
  const float* Wdef = (const float*)d_in[11];
  const float* Wg1  = (const float*)d_in[12];
  const float* bg1  = (const float*)d_in[13];
  const float* Wg2  = (const float*)d_in[14];
  const float* bg2  = (const float*)d_in[15];
  float* out = (float*)d_out;

  void* comp = nullptr; void* part = nullptr; void* enh = nullptr; void* xh = nullptr;
  cudaGetSymbolAddress(&comp, g_comp);
  cudaGetSymbolAddress(&part, g_part);
  cudaGetSymbolAddress(&enh,  g_enh);
  cudaGetSymbolAddress(&xh,   g_xh);

  const int SM_CONV = 66560;
  const int SM_K7   = (16*6*66 + 16*6*64) * 4;   // 49920

  static cudaStream_t s2 = nullptr;
  static cudaEvent_t evFork = nullptr, evJoin = nullptr;
  if (s2 == nullptr) {
    cudaFuncSetAttribute((const void*)conv_mma<256,256,1,0,0,0,1,1>, cudaFuncAttributeMaxDynamicSharedMemorySize, SM_CONV);
    cudaFuncSetAttribute((const void*)conv_mma<64,128,9,2,2,1,0,0>,  cudaFuncAttributeMaxDynamicSharedMemorySize, SM_CONV);
    cudaFuncSetAttribute((const void*)conv_mma<64,256,9,2,1,1,1,0>,  cudaFuncAttributeMaxDynamicSharedMemorySize, SM_CONV);
    cudaFuncSetAttribute((const void*)k7_fused,                      cudaFuncAttributeMaxDynamicSharedMemorySize, SM_K7);
    cudaStreamCreateWithFlags(&s2, cudaStreamNonBlocking);
    cudaEventCreateWithFlags(&evFork, cudaEventDisableTiming);
    cudaEventCreateWithFlags(&evJoin, cudaEventDisableTiming);
  }

  // k1 first (writes g_xh as by-product); then fork k4 (reads g_xh) to side
  conv_mma<256,256,1,0,0,0,1,1><<<dim3(16,2,8), 256, SM_CONV>>>(x, Wkc, comp, bkc);

  cudaEventRecord(evFork, 0);
  cudaStreamWaitEvent(s2, evFork, 0);
  conv_mma<64,256,9,2,1,1,1,0><<<dim3(16,4,8), 256, SM_CONV, s2>>>(xh, Wdef, enh, nullptr);

  conv_mma<64,128,9,2,2,1,0,0><<<dim3(16,2,8), 256, SM_CONV>>>(comp, Wkp1, part, nullptr);
  k3_kw   <<<512, 256>>>(Wkp2, bkp2, bkp1, g1, be1, m1, v1);
  k3b_gmap<<<128, 256>>>();
  k5b_pool<<<2048, 256>>>();

  // ---- join: k6/k7 need enh + psum + pool_x ----
  cudaEventRecord(evJoin, s2);
  cudaStreamWaitEvent(0, evJoin, 0);

  k6_gate <<<8, 256>>>(Wg1, bg1, Wg2, bg2);
  k7_fused<<<dim3(16,16,8), 256, SM_K7>>>(out);
}